// round 3
// baseline (speedup 1.0000x reference)
#include <cuda_runtime.h>
#include <math.h>

// ---------------- problem constants ----------------
#define BSZ 1024
#define NN  7
#define DD  1024
#define MROWS (BSZ*NN)        // 7168

// output layout (tuple flattened in order):
// fused (B*D), updated (B*N*D), imp (B*N), attn (B*N*N), phys (1), align (1)
#define OFF_FUSED 0
#define OFF_UPD   (BSZ*DD)                    // 1048576
#define OFF_IMP   (OFF_UPD + BSZ*NN*DD)       // 8388608
#define OFF_ATTN  (OFF_IMP + BSZ*NN)          // 8395776
#define OFF_PHYS  (OFF_ATTN + BSZ*NN*NN)      // 8445952
#define OFF_ALIGN (OFF_PHYS + 1)              // 8445953

// ---------------- scratch (allocation-free: __device__ globals) ----------------
__device__ float pg_q  [MROWS*DD];
__device__ float pg_k  [MROWS*DD];
__device__ float pg_v  [MROWS*DD];
__device__ float pg_la [MROWS*DD];
__device__ float pg_rb [MROWS*DD];
__device__ float pg_cc [BSZ*DD];
__device__ float pg_msg[MROWS*DD];
__device__ float pg_h1 [MROWS*DD];
__device__ float pg_h2 [MROWS*DD];
__device__ float pg_gq [MROWS*DD];
__device__ float pg_part[BSZ*3];

// ADJ matrix
__constant__ float c_adj[49] = {
    1,1,0,0,1,1,1,
    1,1,1,1,1,1,1,
    0,1,1,0,1,0,1,
    0,1,0,1,1,1,1,
    1,1,1,1,1,1,1,
    1,1,0,1,1,1,1,
    1,1,1,1,1,1,1};

__device__ __forceinline__ float gelu_f(float x) {
    return 0.5f * x * (1.0f + erff(x * 0.70710678118654752440f));
}

// ---------------- generic SGEMM: C[M,1024] = concatA[M,K] @ W[K,1024] (+bias)(+gelu|+res) ----------------
#define EPI_NONE 0
#define EPI_GELU 1
#define EPI_RES  2

__global__ __launch_bounds__(256, 2)
void sgemm_kernel(const float* __restrict__ A0, int lda0,
                  const float* __restrict__ A1, int lda1, int ksplit,
                  const float* __restrict__ W,
                  const float* __restrict__ bias,
                  const float* __restrict__ R,
                  float* __restrict__ C,
                  int K, int epi)
{
    __shared__ float As[8][128];
    __shared__ float Bs[8][128];
    const int tid = threadIdx.x;
    const int ty = tid >> 4, tx = tid & 15;
    const int m0 = blockIdx.y * 128;
    const int n0 = blockIdx.x * 128;

    float acc[8][8];
#pragma unroll
    for (int i = 0; i < 8; i++)
#pragma unroll
        for (int j = 0; j < 8; j++) acc[i][j] = 0.f;

    const int ar  = tid >> 1;          // 0..127 row within A tile
    const int akq = (tid & 1) * 4;     // 0 or 4
    const int wkr = tid >> 5;          // 0..7
    const int wnc = (tid & 31) * 4;    // 0..124

    for (int k0 = 0; k0 < K; k0 += 8) {
        const int kc = k0 + akq;
        const float* ap;
        if (kc < ksplit) ap = A0 + (size_t)(m0 + ar) * lda0 + kc;
        else             ap = A1 + (size_t)(m0 + ar) * lda1 + (kc - ksplit);
        float4 av = *(const float4*)ap;
        As[akq + 0][ar] = av.x; As[akq + 1][ar] = av.y;
        As[akq + 2][ar] = av.z; As[akq + 3][ar] = av.w;

        float4 wv = *(const float4*)(W + (size_t)(k0 + wkr) * 1024 + n0 + wnc);
        *(float4*)&Bs[wkr][wnc] = wv;
        __syncthreads();

#pragma unroll
        for (int kk = 0; kk < 8; kk++) {
            float a[8], bb[8];
#pragma unroll
            for (int i = 0; i < 8; i++) a[i]  = As[kk][ty * 8 + i];
#pragma unroll
            for (int j = 0; j < 8; j++) bb[j] = Bs[kk][tx * 8 + j];
#pragma unroll
            for (int i = 0; i < 8; i++)
#pragma unroll
                for (int j = 0; j < 8; j++)
                    acc[i][j] = fmaf(a[i], bb[j], acc[i][j]);
        }
        __syncthreads();
    }

    float bvv[8];
#pragma unroll
    for (int j = 0; j < 8; j++) bvv[j] = bias ? bias[n0 + tx * 8 + j] : 0.f;

#pragma unroll
    for (int i = 0; i < 8; i++) {
        const int row = m0 + ty * 8 + i;
        float* crow = C + (size_t)row * 1024 + n0 + tx * 8;
        const float* rrow = (epi == EPI_RES) ? (R + (size_t)row * 1024 + n0 + tx * 8) : nullptr;
#pragma unroll
        for (int j = 0; j < 8; j++) {
            float cv = acc[i][j] + bvv[j];
            if (epi == EPI_GELU)      cv = gelu_f(cv);
            else if (epi == EPI_RES)  cv += rrow[j];
            crow[j] = cv;
        }
    }
}

// ---------------- fused attention (per batch): qk logits + edge MLP + mask + softmax + messages ----------------
__global__ void attn_kernel(const float* __restrict__ q, const float* __restrict__ k,
                            const float* __restrict__ v, const float* __restrict__ la,
                            const float* __restrict__ rb, const float* __restrict__ cc,
                            const float* __restrict__ be1, const float* __restrict__ We2,
                            const float* __restrict__ be2,
                            float* __restrict__ attn_out, float* __restrict__ msg)
{
    const int b = blockIdx.x;
    extern __shared__ float sm[];
    float* sq  = sm;               // 7*1024
    float* sk  = sq  + NN * DD;
    float* sv  = sk  + NN * DD;
    float* sla = sv  + NN * DD;
    float* srb = sla + NN * DD;
    float* scc = srb + NN * DD;    // 1024
    float* sbe = scc + DD;         // 1024
    float* sw2 = sbe + DD;         // 1024
    __shared__ float s_logits[49];
    __shared__ float s_attn[49];

    const int tid = threadIdx.x;
    const size_t base = (size_t)b * NN * DD;
    for (int i = tid; i < NN * DD; i += 256) {
        sq[i]  = q[base + i];
        sk[i]  = k[base + i];
        sv[i]  = v[base + i];
        sla[i] = la[base + i];
        srb[i] = rb[base + i];
    }
    for (int i = tid; i < DD; i += 256) {
        scc[i] = cc[(size_t)b * DD + i];
        sbe[i] = be1[i];
        sw2[i] = We2[i];
    }
    __syncthreads();

    const int warp = tid >> 5, lane = tid & 31;
    const float be2v = be2[0];
    for (int p = warp; p < 49; p += 8) {
        const int n = p / 7, m = p % 7;
        float aqk = 0.f, ae = 0.f;
        for (int d = lane; d < DD; d += 32) {
            aqk = fmaf(sq[n * DD + d], sk[m * DD + d], aqk);
            float x = sla[n * DD + d] + srb[m * DD + d] + scc[d] + sbe[d];
            ae = fmaf(gelu_f(x), sw2[d], ae);
        }
#pragma unroll
        for (int o = 16; o; o >>= 1) {
            aqk += __shfl_xor_sync(0xffffffffu, aqk, o);
            ae  += __shfl_xor_sync(0xffffffffu, ae,  o);
        }
        if (lane == 0)
            s_logits[p] = aqk * (1.0f / 32.0f) + ae + be2v + (c_adj[p] - 1.0f) * 10000.0f;
    }
    __syncthreads();

    if (tid < 7) {
        const int n = tid;
        float mx = -1e30f;
#pragma unroll
        for (int m = 0; m < 7; m++) mx = fmaxf(mx, s_logits[n * 7 + m]);
        float s = 0.f;
        float e[7];
#pragma unroll
        for (int m = 0; m < 7; m++) { e[m] = expf(s_logits[n * 7 + m] - mx); s += e[m]; }
        const float inv = 1.0f / s;
#pragma unroll
        for (int m = 0; m < 7; m++) {
            const float a = e[m] * inv;
            s_attn[n * 7 + m] = a;
            attn_out[(size_t)b * 49 + n * 7 + m] = a;
        }
    }
    __syncthreads();

    for (int i = tid; i < NN * DD; i += 256) {
        const int n = i >> 10, d = i & 1023;
        float s = 0.f;
#pragma unroll
        for (int m = 0; m < 7; m++) s = fmaf(s_attn[n * 7 + m], sv[m * DD + d], s);
        msg[base + i] = s;
    }
}

// ---------------- gq broadcast copy ----------------
__global__ void gq_copy_kernel(const float* __restrict__ upd, float* __restrict__ gq)
{
    const int idx = blockIdx.x * 256 + threadIdx.x;
    const int r = idx >> 10;
    const int d = idx & 1023;
    const int b = r / 7;
    gq[idx] = upd[(size_t)(b * 7 + 6) * 1024 + d];
}

// ---------------- per-batch finalize: imp logits/softmax/cap, fused, loss partials ----------------
__global__ void final_kernel(const float* __restrict__ upd, const float* __restrict__ h2,
                             const float* __restrict__ Wi2, const float* __restrict__ bi2,
                             float* __restrict__ out_fused, float* __restrict__ out_imp,
                             float* __restrict__ part)
{
    const int b = blockIdx.x;
    __shared__ float su[NN * DD];
    __shared__ float sf[DD];
    __shared__ float s_dot[49];
    __shared__ float s_implog[7];
    __shared__ float s_imp[8];
    __shared__ float s_dotf[7];
    __shared__ float s_fn2;

    const int tid = threadIdx.x, warp = tid >> 5, lane = tid & 31;
    const size_t base = (size_t)b * NN * DD;
    for (int i = tid; i < NN * DD; i += 256) su[i] = upd[base + i];
    __syncthreads();

    // pairwise dots (diagonal = squared norms)
    for (int p = warp; p < 49; p += 8) {
        const int n = p / 7, m = p % 7;
        float s = 0.f;
        for (int d = lane; d < DD; d += 32) s = fmaf(su[n * DD + d], su[m * DD + d], s);
#pragma unroll
        for (int o = 16; o; o >>= 1) s += __shfl_xor_sync(0xffffffffu, s, o);
        if (lane == 0) s_dot[p] = s;
    }
    // importance logits
    if (warp < 7) {
        float s = 0.f;
        for (int d = lane; d < DD; d += 32) s = fmaf(h2[base + warp * DD + d], Wi2[d], s);
#pragma unroll
        for (int o = 16; o; o >>= 1) s += __shfl_xor_sync(0xffffffffu, s, o);
        if (lane == 0) s_implog[warp] = s + bi2[0];
    }
    __syncthreads();

    if (tid == 0) {
        float mx = -1e30f;
#pragma unroll
        for (int n = 0; n < 7; n++) mx = fmaxf(mx, s_implog[n]);
        float e[7], sum = 0.f;
#pragma unroll
        for (int n = 0; n < 7; n++) { e[n] = expf(s_implog[n] - mx); sum += e[n]; }
        float imp[7];
#pragma unroll
        for (int n = 0; n < 7; n++) imp[n] = e[n] / sum;
        const float cap[7] = {1.f, 1.f, 1.f, 0.26f, 1.f, 1.f, 0.24f};
        const float fre[7] = {1.f, 1.f, 1.f, 0.f, 1.f, 1.f, 0.f};
        float capped[7], csum = 0.f, fmass = 0.f;
#pragma unroll
        for (int n = 0; n < 7; n++) {
            capped[n] = fminf(imp[n], cap[n]);
            csum += capped[n];
            fmass += imp[n] * fre[n];
        }
        const float residual = fmaxf(1.0f - csum, 0.0f);
        float redis[7], rsum = 0.f;
#pragma unroll
        for (int n = 0; n < 7; n++) {
            const float fs = (fmass > 1e-6f) ? imp[n] * fre[n] / fmaxf(fmass, 1e-6f)
                                             : fre[n] * 0.2f;
            redis[n] = capped[n] + fs * residual;
            rsum += redis[n];
        }
        const float inv = 1.0f / fmaxf(rsum, 1e-6f);
#pragma unroll
        for (int n = 0; n < 7; n++) {
            s_imp[n] = redis[n] * inv;
            out_imp[b * 7 + n] = s_imp[n];
        }
    }
    __syncthreads();

    for (int d = tid; d < DD; d += 256) {
        float f = 0.f;
#pragma unroll
        for (int n = 0; n < 7; n++) f = fmaf(s_imp[n], su[n * DD + d], f);
        sf[d] = f;
        out_fused[(size_t)b * DD + d] = f;
    }
    __syncthreads();

    if (warp < 7) {
        float s = 0.f;
        for (int d = lane; d < DD; d += 32) s = fmaf(su[warp * DD + d], sf[d], s);
#pragma unroll
        for (int o = 16; o; o >>= 1) s += __shfl_xor_sync(0xffffffffu, s, o);
        if (lane == 0) s_dotf[warp] = s;
    } else {
        float s = 0.f;
        for (int d = lane; d < DD; d += 32) s = fmaf(sf[d], sf[d], s);
#pragma unroll
        for (int o = 16; o; o >>= 1) s += __shfl_xor_sync(0xffffffffu, s, o);
        if (lane == 0) s_fn2 = s;
    }
    __syncthreads();

    if (tid == 0) {
        float norm[7];
#pragma unroll
        for (int n = 0; n < 7; n++) norm[n] = sqrtf(s_dot[n * 7 + n]);
        const float fnorm = sqrtf(s_fn2);
        float edge = 0.f, non = 0.f, align = 0.f;
#pragma unroll
        for (int n = 0; n < 7; n++) {
#pragma unroll
            for (int m = 0; m < 7; m++) {
                const float cosv = s_dot[n * 7 + m] / fmaxf(norm[n] * norm[m], 1e-8f);
                const float adj = c_adj[n * 7 + m];
                edge += (1.0f - cosv) * adj;
                if (n != m) non += fmaxf(cosv - 0.35f, 0.0f) * (1.0f - adj);
            }
            align += 1.0f - s_dotf[n] / (fmaxf(norm[n], 1e-12f) * fmaxf(fnorm, 1e-12f));
        }
        part[b * 3 + 0] = edge;
        part[b * 3 + 1] = non;
        part[b * 3 + 2] = align;
    }
}

// ---------------- deterministic loss reduction ----------------
__global__ void loss_reduce_kernel(const float* __restrict__ part, float* __restrict__ out)
{
    __shared__ float se[256], sn[256], sa[256];
    const int t = threadIdx.x;
    float e = 0.f, n = 0.f, a = 0.f;
    for (int i = t; i < BSZ; i += 256) {
        e += part[i * 3 + 0];
        n += part[i * 3 + 1];
        a += part[i * 3 + 2];
    }
    se[t] = e; sn[t] = n; sa[t] = a;
    __syncthreads();
    for (int s = 128; s; s >>= 1) {
        if (t < s) { se[t] += se[t + s]; sn[t] += sn[t + s]; sa[t] += sa[t + s]; }
        __syncthreads();
    }
    if (t == 0) {
        out[OFF_PHYS]  = se[0] / 41.0f + 0.5f * (sn[0] / 8.0f);
        out[OFF_ALIGN] = sa[0] / 7168.0f;
    }
}

// ---------------- host launch ----------------
extern "C" void kernel_launch(void* const* d_in, const int* in_sizes, int n_in,
                              void* d_out, int out_size)
{
    (void)in_sizes; (void)n_in; (void)out_size;
    const float* nodes = (const float*)d_in[0];
    const float* Wq  = (const float*)d_in[1];  const float* bq  = (const float*)d_in[2];
    const float* Wk  = (const float*)d_in[3];  const float* bk  = (const float*)d_in[4];
    const float* Wv  = (const float*)d_in[5];  const float* bv  = (const float*)d_in[6];
    const float* We1 = (const float*)d_in[7];  const float* be1 = (const float*)d_in[8];
    const float* We2 = (const float*)d_in[9];  const float* be2 = (const float*)d_in[10];
    const float* Wu1 = (const float*)d_in[11]; const float* bu1 = (const float*)d_in[12];
    const float* Wu2 = (const float*)d_in[13]; const float* bu2 = (const float*)d_in[14];
    const float* Wi1 = (const float*)d_in[15]; const float* bi1 = (const float*)d_in[16];
    const float* Wi2 = (const float*)d_in[17]; const float* bi2 = (const float*)d_in[18];
    float* out = (float*)d_out;

    float *pq, *pk, *pv, *pla, *prb, *pcc, *pmsg, *ph1, *ph2, *pgq, *ppart;
    cudaGetSymbolAddress((void**)&pq,   pg_q);
    cudaGetSymbolAddress((void**)&pk,   pg_k);
    cudaGetSymbolAddress((void**)&pv,   pg_v);
    cudaGetSymbolAddress((void**)&pla,  pg_la);
    cudaGetSymbolAddress((void**)&prb,  pg_rb);
    cudaGetSymbolAddress((void**)&pcc,  pg_cc);
    cudaGetSymbolAddress((void**)&pmsg, pg_msg);
    cudaGetSymbolAddress((void**)&ph1,  pg_h1);
    cudaGetSymbolAddress((void**)&ph2,  pg_h2);
    cudaGetSymbolAddress((void**)&pgq,  pg_gq);
    cudaGetSymbolAddress((void**)&ppart, pg_part);

    const dim3 blk(256);
    const dim3 grid_big(8, MROWS / 128);   // (8, 56)
    const dim3 grid_cc(8, BSZ / 128);      // (8, 8)
    const int BIGK = 1 << 30;

    // q, k, v
    sgemm_kernel<<<grid_big, blk>>>(nodes, DD, nullptr, 0, BIGK, Wq, bq, nullptr, pq, DD, EPI_NONE);
    sgemm_kernel<<<grid_big, blk>>>(nodes, DD, nullptr, 0, BIGK, Wk, bk, nullptr, pk, DD, EPI_NONE);
    sgemm_kernel<<<grid_big, blk>>>(nodes, DD, nullptr, 0, BIGK, Wv, bv, nullptr, pv, DD, EPI_NONE);
    // la = nodes@We1[:D], rb = nodes@We1[D:2D], cc = nodes[:,-1]@We1[2D:]
    sgemm_kernel<<<grid_big, blk>>>(nodes, DD, nullptr, 0, BIGK, We1,            nullptr, nullptr, pla, DD, EPI_NONE);
    sgemm_kernel<<<grid_big, blk>>>(nodes, DD, nullptr, 0, BIGK, We1 + DD * DD,  nullptr, nullptr, prb, DD, EPI_NONE);
    sgemm_kernel<<<grid_cc,  blk>>>(nodes + 6 * DD, NN * DD, nullptr, 0, BIGK, We1 + 2 * DD * DD, nullptr, nullptr, pcc, DD, EPI_NONE);

    // fused attention + edge MLP + messages
    const int attn_smem = (5 * NN * DD + 3 * DD) * (int)sizeof(float);  // 155648
    cudaFuncSetAttribute(attn_kernel, cudaFuncAttributeMaxDynamicSharedMemorySize, attn_smem);
    attn_kernel<<<BSZ, blk, attn_smem>>>(pq, pk, pv, pla, prb, pcc, be1, We2, be2,
                                         out + OFF_ATTN, pmsg);

    // h1 = gelu(concat(nodes, msg) @ Wu1 + bu1)
    sgemm_kernel<<<grid_big, blk>>>(nodes, DD, pmsg, DD, DD, Wu1, bu1, nullptr, ph1, 2 * DD, EPI_GELU);
    // updated = h1 @ Wu2 + bu2 + nodes   -> written straight to output
    sgemm_kernel<<<grid_big, blk>>>(ph1, DD, nullptr, 0, BIGK, Wu2, bu2, nodes, out + OFF_UPD, DD, EPI_RES);

    // gq broadcast
    gq_copy_kernel<<<(MROWS * DD) / 256, blk>>>(out + OFF_UPD, pgq);
    // h2 = gelu(concat(updated, gq) @ Wi1 + bi1)
    sgemm_kernel<<<grid_big, blk>>>(out + OFF_UPD, DD, pgq, DD, DD, Wi1, bi1, nullptr, ph2, 2 * DD, EPI_GELU);

    // finalize: imp, fused, loss partials
    final_kernel<<<BSZ, blk>>>(out + OFF_UPD, ph2, Wi2, bi2, out + OFF_FUSED, out + OFF_IMP, ppart);
    loss_reduce_kernel<<<1, blk>>>(ppart, out);
}

// round 10
// speedup vs baseline: 2.0964x; 2.0964x over previous
#include <cuda_runtime.h>
#include <cuda_bf16.h>
#include <math.h>
#include <stdint.h>

#define BSZ 1024
#define NN  7
#define DD  1024
#define MR  (BSZ*NN)

#define OFF_UPD   (BSZ*DD)
#define OFF_IMP   (OFF_UPD + BSZ*NN*DD)
#define OFF_ATTN  (OFF_IMP + BSZ*NN)
#define OFF_PHYS  (OFF_ATTN + BSZ*NN*NN)
#define OFF_ALIGN (OFF_PHYS + 1)

// ---------- scratch ----------
__device__ uint16_t g_w5h [5*1024*1024];   // [Wq|Wk|Wv|Wea|Web]^T hi, [N=5120][K=1024]
__device__ uint16_t g_w5l [5*1024*1024];
__device__ uint16_t g_wech[1024*1024];
__device__ uint16_t g_wecl[1024*1024];
__device__ uint16_t g_wu1h[1024*2048];
__device__ uint16_t g_wu1l[1024*2048];
__device__ uint16_t g_wu2h[1024*1024];
__device__ uint16_t g_wu2l[1024*1024];
__device__ uint16_t g_wi1h[1024*2048];
__device__ uint16_t g_wi1l[1024*2048];
__device__ float g_c1  [MR*5120];
__device__ float g_cc  [BSZ*DD];
__device__ float g_msg [MR*DD];
__device__ float g_h1  [MR*DD];
__device__ float g_h2  [MR*DD];
__device__ float g_gq  [MR*DD];
__device__ float g_b5  [5120];
__device__ float g_part[BSZ*3];

__constant__ float c_adj[49] = {
    1,1,0,0,1,1,1, 1,1,1,1,1,1,1, 0,1,1,0,1,0,1, 0,1,0,1,1,1,1,
    1,1,1,1,1,1,1, 1,1,0,1,1,1,1, 1,1,1,1,1,1,1};

__device__ __forceinline__ float gelu_f(float x) {
    return 0.5f * x * (1.0f + erff(x * 0.70710678118654752440f));
}
__device__ __forceinline__ void split_bf(float x, uint16_t& h, uint16_t& l) {
    __nv_bfloat16 hb = __float2bfloat16(x);
    float hf = __bfloat162float(hb);
    __nv_bfloat16 lb = __float2bfloat16(x - hf);
    h = __bfloat16_as_ushort(hb);
    l = __bfloat16_as_ushort(lb);
}
__device__ __forceinline__ void mma_bf16(float* c, const uint32_t* a, const uint32_t* b) {
    asm volatile(
        "mma.sync.aligned.m16n8k16.row.col.f32.bf16.bf16.f32 "
        "{%0,%1,%2,%3}, {%4,%5,%6,%7}, {%8,%9}, {%0,%1,%2,%3};"
        : "+f"(c[0]), "+f"(c[1]), "+f"(c[2]), "+f"(c[3])
        : "r"(a[0]), "r"(a[1]), "r"(a[2]), "r"(a[3]), "r"(b[0]), "r"(b[1]));
}

// ---------- split-bf16 tensor-core GEMM ----------
// C[M,Ncols] = concatA[M,K](fp32) @ Bt[Ncols,K](bf16 hi/lo)^T
// 128x128 tile, 32-k chunk, 2-stage smem double buffer, 8 warps (4x2), warp tile 32x64
#define SH   40                   // smem row stride (halves)
#define MATH (128*SH)             // halves per matrix (5120)
#define STAGEH (4*MATH)           // halves per stage (Ah,Al,Bh,Bl)

__global__ __launch_bounds__(256, 1)
void gemm_bfs(const float* __restrict__ A0, int lda0,
              const float* __restrict__ A1, int lda1, int ksplit,
              const uint16_t* __restrict__ Bh, const uint16_t* __restrict__ Bl,
              const float* __restrict__ bias, const float* __restrict__ Rres,
              float* __restrict__ C, int ldc, int K, int epi)
{
    extern __shared__ __align__(16) uint16_t sh[];  // [2][4][128][SH]
    const int tid = threadIdx.x, wid = tid >> 5, lane = tid & 31;
    const int m0 = blockIdx.y * 128, n0 = blockIdx.x * 128;
    const int NC = K / 32;
    const int wm = wid & 3, wn = wid >> 2;
    const int gid = lane >> 2, tig = lane & 3;

    const int lrow = tid >> 1;            // 0..127
    const int kb0  = (tid & 1) * 16;      // 0 or 16

    float acc[2][8][4];
#pragma unroll
    for (int i = 0; i < 2; i++)
#pragma unroll
        for (int j = 0; j < 8; j++)
#pragma unroll
            for (int q = 0; q < 4; q++) acc[i][j][q] = 0.f;

    float4 ra[4];
    uint4  rbh[2], rbl[2];

#define LOADG(c) do { \
    const int _k0 = (c) * 32; \
    const float* _ap; int _ld; \
    if (_k0 < ksplit) { _ap = A0 + (size_t)(m0 + lrow) * lda0 + _k0;            _ld = lda0; } \
    else              { _ap = A1 + (size_t)(m0 + lrow) * lda1 + (_k0 - ksplit); _ld = lda1; } \
    (void)_ld; \
    _Pragma("unroll") \
    for (int _j = 0; _j < 4; _j++) ra[_j] = *(const float4*)(_ap + kb0 + 4 * _j); \
    const size_t _bo = (size_t)(n0 + lrow) * K + _k0 + kb0; \
    rbh[0] = *(const uint4*)(Bh + _bo);     rbh[1] = *(const uint4*)(Bh + _bo + 8); \
    rbl[0] = *(const uint4*)(Bl + _bo);     rbl[1] = *(const uint4*)(Bl + _bo + 8); \
} while (0)

#define STS_STAGE(st) do { \
    uint16_t* _base = sh + (st) * STAGEH; \
    uint16_t _h[16], _l[16]; \
    _Pragma("unroll") \
    for (int _j = 0; _j < 4; _j++) { \
        split_bf(ra[_j].x, _h[4*_j+0], _l[4*_j+0]); \
        split_bf(ra[_j].y, _h[4*_j+1], _l[4*_j+1]); \
        split_bf(ra[_j].z, _h[4*_j+2], _l[4*_j+2]); \
        split_bf(ra[_j].w, _h[4*_j+3], _l[4*_j+3]); \
    } \
    const int _off = lrow * SH + kb0; \
    _Pragma("unroll") \
    for (int _j = 0; _j < 2; _j++) { \
        *(uint4*)(_base + _off + 8*_j)          = *(uint4*)&_h[8*_j]; \
        *(uint4*)(_base + MATH + _off + 8*_j)   = *(uint4*)&_l[8*_j]; \
        *(uint4*)(_base + 2*MATH + _off + 8*_j) = rbh[_j]; \
        *(uint4*)(_base + 3*MATH + _off + 8*_j) = rbl[_j]; \
    } \
} while (0)

    LOADG(0);
    STS_STAGE(0);
    __syncthreads();

    for (int c = 0; c < NC; c++) {
        if (c + 1 < NC) LOADG(c + 1);

        const uint16_t* sa = sh + (c & 1) * STAGEH;
#pragma unroll
        for (int ks = 0; ks < 2; ks++) {
            const int kk = ks * 16 + 2 * tig;
            uint32_t aH[2][4], aL[2][4], bH[8][2], bL[8][2];
#pragma unroll
            for (int mt = 0; mt < 2; mt++) {
                const int rb = (wm * 32 + mt * 16 + gid) * SH + kk;
                aH[mt][0] = *(const uint32_t*)(sa + rb);
                aH[mt][1] = *(const uint32_t*)(sa + rb + 8 * SH);
                aH[mt][2] = *(const uint32_t*)(sa + rb + 8);
                aH[mt][3] = *(const uint32_t*)(sa + rb + 8 * SH + 8);
                aL[mt][0] = *(const uint32_t*)(sa + MATH + rb);
                aL[mt][1] = *(const uint32_t*)(sa + MATH + rb + 8 * SH);
                aL[mt][2] = *(const uint32_t*)(sa + MATH + rb + 8);
                aL[mt][3] = *(const uint32_t*)(sa + MATH + rb + 8 * SH + 8);
            }
#pragma unroll
            for (int nt = 0; nt < 8; nt++) {
                const int nr = (wn * 64 + nt * 8 + gid) * SH + kk;
                bH[nt][0] = *(const uint32_t*)(sa + 2 * MATH + nr);
                bH[nt][1] = *(const uint32_t*)(sa + 2 * MATH + nr + 8);
                bL[nt][0] = *(const uint32_t*)(sa + 3 * MATH + nr);
                bL[nt][1] = *(const uint32_t*)(sa + 3 * MATH + nr + 8);
            }
#pragma unroll
            for (int mt = 0; mt < 2; mt++)
#pragma unroll
                for (int nt = 0; nt < 8; nt++) {
                    mma_bf16(acc[mt][nt], aH[mt], bH[nt]);
                    mma_bf16(acc[mt][nt], aL[mt], bH[nt]);
                    mma_bf16(acc[mt][nt], aH[mt], bL[nt]);
                }
        }

        if (c + 1 < NC) STS_STAGE((c + 1) & 1);
        __syncthreads();
    }

    // epilogue: c0,c1 -> (row=gid, col=2tig,+1); c2,c3 -> row gid+8
#pragma unroll
    for (int mt = 0; mt < 2; mt++) {
#pragma unroll
        for (int rr = 0; rr < 2; rr++) {
            const int row = m0 + wm * 32 + mt * 16 + gid + rr * 8;
#pragma unroll
            for (int nt = 0; nt < 8; nt++) {
                const int col = n0 + wn * 64 + nt * 8 + tig * 2;
                float v0 = acc[mt][nt][rr * 2 + 0];
                float v1 = acc[mt][nt][rr * 2 + 1];
                if (bias) { v0 += bias[col]; v1 += bias[col + 1]; }
                if (epi == 1) { v0 = gelu_f(v0); v1 = gelu_f(v1); }
                else if (epi == 2) {
                    const float2 rv = *(const float2*)(Rres + (size_t)row * 1024 + col);
                    v0 += rv.x; v1 += rv.y;
                }
                *(float2*)(C + (size_t)row * ldc + col) = make_float2(v0, v1);
            }
        }
    }
}

// ---------- transpose + bf16 split: W[K,1024] -> Wth/Wtl[1024,K] ----------
__global__ void transpose_split(const float* __restrict__ W,
                                uint16_t* __restrict__ Oh, uint16_t* __restrict__ Ol, int K)
{
    __shared__ float t[32][33];
    const int k0 = blockIdx.x * 32, n0 = blockIdx.y * 32;
    const int tx = threadIdx.x & 31, ty = threadIdx.x >> 5;
    for (int i = ty; i < 32; i += 8) t[i][tx] = W[(size_t)(k0 + i) * 1024 + n0 + tx];
    __syncthreads();
    for (int i = ty; i < 32; i += 8) {
        uint16_t h, l;
        split_bf(t[tx][i], h, l);
        const size_t o = (size_t)(n0 + i) * K + k0 + tx;
        Oh[o] = h; Ol[o] = l;
    }
}

__global__ void biascat(const float* __restrict__ bq, const float* __restrict__ bk,
                        const float* __restrict__ bv, float* __restrict__ o)
{
    const int i = blockIdx.x * 256 + threadIdx.x;
    float v = 0.f;
    if (i < 1024) v = bq[i];
    else if (i < 2048) v = bk[i - 1024];
    else if (i < 3072) v = bv[i - 2048];
    o[i] = v;
}

// ---------- fused attention ----------
__global__ void attn_kernel(const float* __restrict__ c1, const float* __restrict__ cc,
                            const float* __restrict__ be1, const float* __restrict__ We2,
                            const float* __restrict__ be2,
                            float* __restrict__ attn_out, float* __restrict__ msg)
{
    const int b = blockIdx.x;
    extern __shared__ float sm[];
    float* sq  = sm;
    float* sk  = sq  + NN * DD;
    float* sv  = sk  + NN * DD;
    float* sla = sv  + NN * DD;
    float* srb = sla + NN * DD;
    float* scc = srb + NN * DD;
    float* sbe = scc + DD;
    float* sw2 = sbe + DD;
    __shared__ float s_logits[49];
    __shared__ float s_attn[49];

    const int tid = threadIdx.x;
    const size_t rbase = (size_t)b * NN * 5120;
    for (int i = tid; i < NN * DD; i += 256) {
        const int n = i >> 10, d = i & 1023;
        const size_t ro = rbase + (size_t)n * 5120 + d;
        sq[i]  = c1[ro];
        sk[i]  = c1[ro + 1024];
        sv[i]  = c1[ro + 2048];
        sla[i] = c1[ro + 3072];
        srb[i] = c1[ro + 4096];
    }
    for (int i = tid; i < DD; i += 256) {
        scc[i] = cc[(size_t)b * DD + i];
        sbe[i] = be1[i];
        sw2[i] = We2[i];
    }
    __syncthreads();

    const int warp = tid >> 5, lane = tid & 31;
    const float be2v = be2[0];
    for (int p = warp; p < 49; p += 8) {
        const int n = p / 7, m = p % 7;
        float aqk = 0.f, ae = 0.f;
        for (int d = lane; d < DD; d += 32) {
            aqk = fmaf(sq[n * DD + d], sk[m * DD + d], aqk);
            const float x = sla[n * DD + d] + srb[m * DD + d] + scc[d] + sbe[d];
            ae = fmaf(gelu_f(x), sw2[d], ae);
        }
#pragma unroll
        for (int o = 16; o; o >>= 1) {
            aqk += __shfl_xor_sync(0xffffffffu, aqk, o);
            ae  += __shfl_xor_sync(0xffffffffu, ae,  o);
        }
        if (lane == 0)
            s_logits[p] = aqk * (1.0f / 32.0f) + ae + be2v + (c_adj[p] - 1.0f) * 10000.0f;
    }
    __syncthreads();

    if (tid < 7) {
        const int n = tid;
        float mx = -1e30f;
#pragma unroll
        for (int m = 0; m < 7; m++) mx = fmaxf(mx, s_logits[n * 7 + m]);
        float s = 0.f, e[7];
#pragma unroll
        for (int m = 0; m < 7; m++) { e[m] = expf(s_logits[n * 7 + m] - mx); s += e[m]; }
        const float inv = 1.0f / s;
#pragma unroll
        for (int m = 0; m < 7; m++) {
            const float a = e[m] * inv;
            s_attn[n * 7 + m] = a;
            attn_out[(size_t)b * 49 + n * 7 + m] = a;
        }
    }
    __syncthreads();

    const size_t obase = (size_t)b * NN * DD;
    for (int i = tid; i < NN * DD; i += 256) {
        const int n = i >> 10, d = i & 1023;
        float s = 0.f;
#pragma unroll
        for (int m = 0; m < 7; m++) s = fmaf(s_attn[n * 7 + m], sv[m * DD + d], s);
        msg[obase + i] = s;
    }
}

__global__ void gq_copy_kernel(const float* __restrict__ upd, float* __restrict__ gq)
{
    const int idx = blockIdx.x * 256 + threadIdx.x;
    const int r = idx >> 10, d = idx & 1023, b = r / 7;
    gq[idx] = upd[(size_t)(b * 7 + 6) * 1024 + d];
}

// ---------- finalize ----------
__global__ void final_kernel(const float* __restrict__ upd, const float* __restrict__ h2,
                             const float* __restrict__ Wi2, const float* __restrict__ bi2,
                             float* __restrict__ out_fused, float* __restrict__ out_imp,
                             float* __restrict__ part)
{
    const int b = blockIdx.x;
    __shared__ float su[NN * DD];
    __shared__ float sf[DD];
    __shared__ float s_dot[49], s_implog[7], s_imp[8], s_dotf[7], s_fn2[1];

    const int tid = threadIdx.x, warp = tid >> 5, lane = tid & 31;
    const size_t base = (size_t)b * NN * DD;
    for (int i = tid; i < NN * DD; i += 256) su[i] = upd[base + i];
    __syncthreads();

    for (int p = warp; p < 49; p += 8) {
        const int n = p / 7, m = p % 7;
        float s = 0.f;
        for (int d = lane; d < DD; d += 32) s = fmaf(su[n * DD + d], su[m * DD + d], s);
#pragma unroll
        for (int o = 16; o; o >>= 1) s += __shfl_xor_sync(0xffffffffu, s, o);
        if (lane == 0) s_dot[p] = s;
    }
    if (warp < 7) {
        float s = 0.f;
        for (int d = lane; d < DD; d += 32) s = fmaf(h2[base + warp * DD + d], Wi2[d], s);
#pragma unroll
        for (int o = 16; o; o >>= 1) s += __shfl_xor_sync(0xffffffffu, s, o);
        if (lane == 0) s_implog[warp] = s + bi2[0];
    }
    __syncthreads();

    if (tid == 0) {
        float mx = -1e30f;
#pragma unroll
        for (int n = 0; n < 7; n++) mx = fmaxf(mx, s_implog[n]);
        float e[7], sum = 0.f;
#pragma unroll
        for (int n = 0; n < 7; n++) { e[n] = expf(s_implog[n] - mx); sum += e[n]; }
        float imp[7];
#pragma unroll
        for (int n = 0; n < 7; n++) imp[n] = e[n] / sum;
        const float cap[7] = {1.f,1.f,1.f,0.26f,1.f,1.f,0.24f};
        const float fre[7] = {1.f,1.f,1.f,0.f,1.f,1.f,0.f};
        float capped[7], csum = 0.f, fmass = 0.f;
#pragma unroll
        for (int n = 0; n < 7; n++) {
            capped[n] = fminf(imp[n], cap[n]);
            csum += capped[n]; fmass += imp[n] * fre[n];
        }
        const float residual = fmaxf(1.0f - csum, 0.0f);
        float redis[7], rsum = 0.f;
#pragma unroll
        for (int n = 0; n < 7; n++) {
            const float fs = (fmass > 1e-6f) ? imp[n] * fre[n] / fmaxf(fmass, 1e-6f)
                                             : fre[n] * 0.2f;
            redis[n] = capped[n] + fs * residual;
            rsum += redis[n];
        }
        const float inv = 1.0f / fmaxf(rsum, 1e-6f);
#pragma unroll
        for (int n = 0; n < 7; n++) { s_imp[n] = redis[n] * inv; out_imp[b * 7 + n] = s_imp[n]; }
    }
    __syncthreads();

    for (int d = tid; d < DD; d += 256) {
        float f = 0.f;
#pragma unroll
        for (int n = 0; n < 7; n++) f = fmaf(s_imp[n], su[n * DD + d], f);
        sf[d] = f;
        out_fused[(size_t)b * DD + d] = f;
    }
    __syncthreads();

    if (warp < 7) {
        float s = 0.f;
        for (int d = lane; d < DD; d += 32) s = fmaf(su[warp * DD + d], sf[d], s);
#pragma unroll
        for (int o = 16; o; o >>= 1) s += __shfl_xor_sync(0xffffffffu, s, o);
        if (lane == 0) s_dotf[warp] = s;
    } else if (warp == 7) {
        float s = 0.f;
        for (int d = lane; d < DD; d += 32) s = fmaf(sf[d], sf[d], s);
#pragma unroll
        for (int o = 16; o; o >>= 1) s += __shfl_xor_sync(0xffffffffu, s, o);
        if (lane == 0) s_fn2[0] = s;
    }
    __syncthreads();

    if (tid == 0) {
        float norm[7];
#pragma unroll
        for (int n = 0; n < 7; n++) norm[n] = sqrtf(s_dot[n * 7 + n]);
        const float fnorm = sqrtf(s_fn2[0]);
        float edge = 0.f, non = 0.f, align = 0.f;
#pragma unroll
        for (int n = 0; n < 7; n++) {
#pragma unroll
            for (int m = 0; m < 7; m++) {
                const float cosv = s_dot[n * 7 + m] / fmaxf(norm[n] * norm[m], 1e-8f);
                const float adj = c_adj[n * 7 + m];
                edge += (1.0f - cosv) * adj;
                if (n != m) non += fmaxf(cosv - 0.35f, 0.0f) * (1.0f - adj);
            }
            align += 1.0f - s_dotf[n] / (fmaxf(norm[n], 1e-12f) * fmaxf(fnorm, 1e-12f));
        }
        part[b * 3 + 0] = edge; part[b * 3 + 1] = non; part[b * 3 + 2] = align;
    }
}

__global__ void loss_reduce_kernel(const float* __restrict__ part, float* __restrict__ out)
{
    __shared__ float se[256], sn[256], sa[256];
    const int t = threadIdx.x;
    float e = 0.f, n = 0.f, a = 0.f;
    for (int i = t; i < BSZ; i += 256) {
        e += part[i * 3 + 0]; n += part[i * 3 + 1]; a += part[i * 3 + 2];
    }
    se[t] = e; sn[t] = n; sa[t] = a;
    __syncthreads();
    for (int s = 128; s; s >>= 1) {
        if (t < s) { se[t] += se[t+s]; sn[t] += sn[t+s]; sa[t] += sa[t+s]; }
        __syncthreads();
    }
    if (t == 0) {
        out[OFF_PHYS]  = se[0] / 41.0f + 0.5f * (sn[0] / 8.0f);
        out[OFF_ALIGN] = sa[0] / 7168.0f;
    }
}

// ---------- host ----------
extern "C" void kernel_launch(void* const* d_in, const int* in_sizes, int n_in,
                              void* d_out, int out_size)
{
    (void)in_sizes; (void)n_in; (void)out_size;
    const float* nodes = (const float*)d_in[0];
    const float* Wq  = (const float*)d_in[1];  const float* bq  = (const float*)d_in[2];
    const float* Wk  = (const float*)d_in[3];  const float* bk  = (const float*)d_in[4];
    const float* Wv  = (const float*)d_in[5];  const float* bv  = (const float*)d_in[6];
    const float* We1 = (const float*)d_in[7];  const float* be1 = (const float*)d_in[8];
    const float* We2 = (const float*)d_in[9];  const float* be2 = (const float*)d_in[10];
    const float* Wu1 = (const float*)d_in[11]; const float* bu1 = (const float*)d_in[12];
    const float* Wu2 = (const float*)d_in[13]; const float* bu2 = (const float*)d_in[14];
    const float* Wi1 = (const float*)d_in[15]; const float* bi1 = (const float*)d_in[16];
    const float* Wi2 = (const float*)d_in[17]; const float* bi2 = (const float*)d_in[18];
    float* out = (float*)d_out;

    uint16_t *w5h, *w5l, *wech, *wecl, *wu1h, *wu1l, *wu2h, *wu2l, *wi1h, *wi1l;
    float *c1, *cc, *msg, *h1, *h2, *gq, *b5, *part;
    cudaGetSymbolAddress((void**)&w5h,  g_w5h);
    cudaGetSymbolAddress((void**)&w5l,  g_w5l);
    cudaGetSymbolAddress((void**)&wech, g_wech);
    cudaGetSymbolAddress((void**)&wecl, g_wecl);
    cudaGetSymbolAddress((void**)&wu1h, g_wu1h);
    cudaGetSymbolAddress((void**)&wu1l, g_wu1l);
    cudaGetSymbolAddress((void**)&wu2h, g_wu2h);
    cudaGetSymbolAddress((void**)&wu2l, g_wu2l);
    cudaGetSymbolAddress((void**)&wi1h, g_wi1h);
    cudaGetSymbolAddress((void**)&wi1l, g_wi1l);
    cudaGetSymbolAddress((void**)&c1,   g_c1);
    cudaGetSymbolAddress((void**)&cc,   g_cc);
    cudaGetSymbolAddress((void**)&msg,  g_msg);
    cudaGetSymbolAddress((void**)&h1,   g_h1);
    cudaGetSymbolAddress((void**)&h2,   g_h2);
    cudaGetSymbolAddress((void**)&gq,   g_gq);
    cudaGetSymbolAddress((void**)&b5,   g_b5);
    cudaGetSymbolAddress((void**)&part, g_part);

    const int SMEMG = 2 * STAGEH * (int)sizeof(uint16_t);   // 81920
    cudaFuncSetAttribute(gemm_bfs, cudaFuncAttributeMaxDynamicSharedMemorySize, SMEMG);
    const int attn_smem = (5 * NN * DD + 3 * DD) * (int)sizeof(float);
    cudaFuncSetAttribute(attn_kernel, cudaFuncAttributeMaxDynamicSharedMemorySize, attn_smem);

    const dim3 blk(256);
    const dim3 tg(32, 32), tg2(64, 32);
    const int M1 = 1024 * 1024;
    transpose_split<<<tg,  blk>>>(Wq,           w5h,          w5l,          1024);
    transpose_split<<<tg,  blk>>>(Wk,           w5h + M1,     w5l + M1,     1024);
    transpose_split<<<tg,  blk>>>(Wv,           w5h + 2 * M1, w5l + 2 * M1, 1024);
    transpose_split<<<tg,  blk>>>(We1,          w5h + 3 * M1, w5l + 3 * M1, 1024);
    transpose_split<<<tg,  blk>>>(We1 + M1,     w5h + 4 * M1, w5l + 4 * M1, 1024);
    transpose_split<<<tg,  blk>>>(We1 + 2 * M1, wech,         wecl,         1024);
    transpose_split<<<tg2, blk>>>(Wu1,          wu1h,         wu1l,         2048);
    transpose_split<<<tg,  blk>>>(Wu2,          wu2h,         wu2l,         1024);
    transpose_split<<<tg2, blk>>>(Wi1,          wi1h,         wi1l,         2048);
    biascat<<<20, blk>>>(bq, bk, bv, b5);

    const int BIGK = 1 << 30;
    // C1[7168,5120] = nodes @ [Wq|Wk|Wv|Wea|Web]
    gemm_bfs<<<dim3(40, 56), blk, SMEMG>>>(nodes, 1024, nullptr, 0, BIGK,
                                           w5h, w5l, b5, nullptr, c1, 5120, 1024, 0);
    // cc[1024,1024] = nodes[:, -1] @ Wec
    gemm_bfs<<<dim3(8, 8), blk, SMEMG>>>(nodes + 6 * 1024, 7168, nullptr, 0, BIGK,
                                         wech, wecl, nullptr, nullptr, cc, 1024, 1024, 0);
    attn_kernel<<<BSZ, blk, attn_smem>>>(c1, cc, be1, We2, be2, out + OFF_ATTN, msg);
    // h1 = gelu(cat(nodes,msg) @ Wu1 + bu1)
    gemm_bfs<<<dim3(8, 56), blk, SMEMG>>>(nodes, 1024, msg, 1024, 1024,
                                          wu1h, wu1l, bu1, nullptr, h1, 1024, 2048, 1);
    // updated = h1 @ Wu2 + bu2 + nodes
    gemm_bfs<<<dim3(8, 56), blk, SMEMG>>>(h1, 1024, nullptr, 0, BIGK,
                                          wu2h, wu2l, bu2, nodes, out + OFF_UPD, 1024, 1024, 2);
    gq_copy_kernel<<<(MR * DD) / 256, blk>>>(out + OFF_UPD, gq);
    // h2 = gelu(cat(updated,gq) @ Wi1 + bi1)
    gemm_bfs<<<dim3(8, 56), blk, SMEMG>>>(out + OFF_UPD, 1024, gq, 1024, 1024,
                                          wi1h, wi1l, bi1, nullptr, h2, 1024, 2048, 1);
    final_kernel<<<BSZ, blk>>>(out + OFF_UPD, h2, Wi2, bi2, out, out + OFF_IMP, part);
    loss_reduce_kernel<<<1, blk>>>(part, out);
}

// round 11
// speedup vs baseline: 2.2236x; 1.0607x over previous
#include <cuda_runtime.h>
#include <cuda_bf16.h>
#include <math.h>
#include <stdint.h>

#define BSZ 1024
#define NN  7
#define DD  1024
#define MR  (BSZ*NN)

#define OFF_UPD   (BSZ*DD)
#define OFF_IMP   (OFF_UPD + BSZ*NN*DD)
#define OFF_ATTN  (OFF_IMP + BSZ*NN)
#define OFF_PHYS  (OFF_ATTN + BSZ*NN*NN)
#define OFF_ALIGN (OFF_PHYS + 1)

// ---------- scratch ----------
__device__ uint16_t g_w5h [5*1024*1024];
__device__ uint16_t g_w5l [5*1024*1024];
__device__ uint16_t g_wech[1024*1024];
__device__ uint16_t g_wecl[1024*1024];
__device__ uint16_t g_wu1h[1024*2048];
__device__ uint16_t g_wu1l[1024*2048];
__device__ uint16_t g_wu2h[1024*1024];
__device__ uint16_t g_wu2l[1024*1024];
__device__ uint16_t g_wi1h[1024*2048];
__device__ uint16_t g_wi1l[1024*2048];
__device__ float g_c1  [MR*5120];
__device__ float g_cc  [BSZ*DD];
__device__ float g_msg [MR*DD];
__device__ float g_h1  [MR*DD];
__device__ float g_h2  [MR*DD];
__device__ float g_gq  [MR*DD];
__device__ float g_b5  [5120];
__device__ float g_part[BSZ*3];

__constant__ float c_adj[49] = {
    1,1,0,0,1,1,1, 1,1,1,1,1,1,1, 0,1,1,0,1,0,1, 0,1,0,1,1,1,1,
    1,1,1,1,1,1,1, 1,1,0,1,1,1,1, 1,1,1,1,1,1,1};
// active (unmasked) pairs: n*7+m where ADJ=1 (41 of 49)
__constant__ int c_pairs[41] = {
    0,1,4,5,6,
    7,8,9,10,11,12,13,
    15,16,18,20,
    22,24,25,26,27,
    28,29,30,31,32,33,34,
    35,36,38,39,40,41,
    42,43,44,45,46,47,48};

// fast gelu: tanh approximation, HW MUFU.TANH (~6 ops vs ~17 for erf path)
__device__ __forceinline__ float gelu_f(float x) {
    const float x2 = x * x;
    const float u = x * fmaf(0.0356774081f, x2, 0.7978845608f);
    float t;
    asm("tanh.approx.f32 %0, %1;" : "=f"(t) : "f"(u));
    const float hx = 0.5f * x;
    return fmaf(hx, t, hx);
}
__device__ __forceinline__ void split_bf(float x, uint16_t& h, uint16_t& l) {
    __nv_bfloat16 hb = __float2bfloat16(x);
    float hf = __bfloat162float(hb);
    __nv_bfloat16 lb = __float2bfloat16(x - hf);
    h = __bfloat16_as_ushort(hb);
    l = __bfloat16_as_ushort(lb);
}
__device__ __forceinline__ void mma_bf16(float* c, const uint32_t* a, const uint32_t* b) {
    asm volatile(
        "mma.sync.aligned.m16n8k16.row.col.f32.bf16.bf16.f32 "
        "{%0,%1,%2,%3}, {%4,%5,%6,%7}, {%8,%9}, {%0,%1,%2,%3};"
        : "+f"(c[0]), "+f"(c[1]), "+f"(c[2]), "+f"(c[3])
        : "r"(a[0]), "r"(a[1]), "r"(a[2]), "r"(a[3]), "r"(b[0]), "r"(b[1]));
}

// ---------- split-bf16 tensor-core GEMM (unchanged mainloop from R10) ----------
#define SH   40
#define MATH (128*SH)
#define STAGEH (4*MATH)

__global__ __launch_bounds__(256, 1)
void gemm_bfs(const float* __restrict__ A0, int lda0,
              const float* __restrict__ A1, int lda1, int ksplit,
              const uint16_t* __restrict__ Bh, const uint16_t* __restrict__ Bl,
              const float* __restrict__ bias, const float* __restrict__ Rres,
              float* __restrict__ C, int ldc, int K, int epi)
{
    extern __shared__ __align__(16) uint16_t sh[];
    const int tid = threadIdx.x, wid = tid >> 5, lane = tid & 31;
    const int m0 = blockIdx.y * 128, n0 = blockIdx.x * 128;
    const int NC = K / 32;
    const int wm = wid & 3, wn = wid >> 2;
    const int gid = lane >> 2, tig = lane & 3;

    const int lrow = tid >> 1;
    const int kb0  = (tid & 1) * 16;

    float acc[2][8][4];
#pragma unroll
    for (int i = 0; i < 2; i++)
#pragma unroll
        for (int j = 0; j < 8; j++)
#pragma unroll
            for (int q = 0; q < 4; q++) acc[i][j][q] = 0.f;

    float4 ra[4];
    uint4  rbh[2], rbl[2];

#define LOADG(c) do { \
    const int _k0 = (c) * 32; \
    const float* _ap; int _ld; \
    if (_k0 < ksplit) { _ap = A0 + (size_t)(m0 + lrow) * lda0 + _k0;            _ld = lda0; } \
    else              { _ap = A1 + (size_t)(m0 + lrow) * lda1 + (_k0 - ksplit); _ld = lda1; } \
    (void)_ld; \
    _Pragma("unroll") \
    for (int _j = 0; _j < 4; _j++) ra[_j] = *(const float4*)(_ap + kb0 + 4 * _j); \
    const size_t _bo = (size_t)(n0 + lrow) * K + _k0 + kb0; \
    rbh[0] = *(const uint4*)(Bh + _bo);     rbh[1] = *(const uint4*)(Bh + _bo + 8); \
    rbl[0] = *(const uint4*)(Bl + _bo);     rbl[1] = *(const uint4*)(Bl + _bo + 8); \
} while (0)

#define STS_STAGE(st) do { \
    uint16_t* _base = sh + (st) * STAGEH; \
    uint16_t _h[16], _l[16]; \
    _Pragma("unroll") \
    for (int _j = 0; _j < 4; _j++) { \
        split_bf(ra[_j].x, _h[4*_j+0], _l[4*_j+0]); \
        split_bf(ra[_j].y, _h[4*_j+1], _l[4*_j+1]); \
        split_bf(ra[_j].z, _h[4*_j+2], _l[4*_j+2]); \
        split_bf(ra[_j].w, _h[4*_j+3], _l[4*_j+3]); \
    } \
    const int _off = lrow * SH + kb0; \
    _Pragma("unroll") \
    for (int _j = 0; _j < 2; _j++) { \
        *(uint4*)(_base + _off + 8*_j)          = *(uint4*)&_h[8*_j]; \
        *(uint4*)(_base + MATH + _off + 8*_j)   = *(uint4*)&_l[8*_j]; \
        *(uint4*)(_base + 2*MATH + _off + 8*_j) = rbh[_j]; \
        *(uint4*)(_base + 3*MATH + _off + 8*_j) = rbl[_j]; \
    } \
} while (0)

    LOADG(0);
    STS_STAGE(0);
    __syncthreads();

    for (int c = 0; c < NC; c++) {
        if (c + 1 < NC) LOADG(c + 1);

        const uint16_t* sa = sh + (c & 1) * STAGEH;
#pragma unroll
        for (int ks = 0; ks < 2; ks++) {
            const int kk = ks * 16 + 2 * tig;
            uint32_t aH[2][4], aL[2][4], bH[8][2], bL[8][2];
#pragma unroll
            for (int mt = 0; mt < 2; mt++) {
                const int rb = (wm * 32 + mt * 16 + gid) * SH + kk;
                aH[mt][0] = *(const uint32_t*)(sa + rb);
                aH[mt][1] = *(const uint32_t*)(sa + rb + 8 * SH);
                aH[mt][2] = *(const uint32_t*)(sa + rb + 8);
                aH[mt][3] = *(const uint32_t*)(sa + rb + 8 * SH + 8);
                aL[mt][0] = *(const uint32_t*)(sa + MATH + rb);
                aL[mt][1] = *(const uint32_t*)(sa + MATH + rb + 8 * SH);
                aL[mt][2] = *(const uint32_t*)(sa + MATH + rb + 8);
                aL[mt][3] = *(const uint32_t*)(sa + MATH + rb + 8 * SH + 8);
            }
#pragma unroll
            for (int nt = 0; nt < 8; nt++) {
                const int nr = (wn * 64 + nt * 8 + gid) * SH + kk;
                bH[nt][0] = *(const uint32_t*)(sa + 2 * MATH + nr);
                bH[nt][1] = *(const uint32_t*)(sa + 2 * MATH + nr + 8);
                bL[nt][0] = *(const uint32_t*)(sa + 3 * MATH + nr);
                bL[nt][1] = *(const uint32_t*)(sa + 3 * MATH + nr + 8);
            }
#pragma unroll
            for (int mt = 0; mt < 2; mt++)
#pragma unroll
                for (int nt = 0; nt < 8; nt++) {
                    mma_bf16(acc[mt][nt], aH[mt], bH[nt]);
                    mma_bf16(acc[mt][nt], aL[mt], bH[nt]);
                    mma_bf16(acc[mt][nt], aH[mt], bL[nt]);
                }
        }

        if (c + 1 < NC) STS_STAGE((c + 1) & 1);
        __syncthreads();
    }

#pragma unroll
    for (int mt = 0; mt < 2; mt++) {
#pragma unroll
        for (int rr = 0; rr < 2; rr++) {
            const int row = m0 + wm * 32 + mt * 16 + gid + rr * 8;
#pragma unroll
            for (int nt = 0; nt < 8; nt++) {
                const int col = n0 + wn * 64 + nt * 8 + tig * 2;
                float v0 = acc[mt][nt][rr * 2 + 0];
                float v1 = acc[mt][nt][rr * 2 + 1];
                if (bias) { v0 += bias[col]; v1 += bias[col + 1]; }
                if (epi == 1) { v0 = gelu_f(v0); v1 = gelu_f(v1); }
                else if (epi == 2) {
                    const float2 rv = *(const float2*)(Rres + (size_t)row * 1024 + col);
                    v0 += rv.x; v1 += rv.y;
                }
                *(float2*)(C + (size_t)row * ldc + col) = make_float2(v0, v1);
            }
        }
    }
}

// ---------- transpose + bf16 split ----------
__global__ void transpose_split(const float* __restrict__ W,
                                uint16_t* __restrict__ Oh, uint16_t* __restrict__ Ol, int K)
{
    __shared__ float t[32][33];
    const int k0 = blockIdx.x * 32, n0 = blockIdx.y * 32;
    const int tx = threadIdx.x & 31, ty = threadIdx.x >> 5;
    for (int i = ty; i < 32; i += 8) t[i][tx] = W[(size_t)(k0 + i) * 1024 + n0 + tx];
    __syncthreads();
    for (int i = ty; i < 32; i += 8) {
        uint16_t h, l;
        split_bf(t[tx][i], h, l);
        const size_t o = (size_t)(n0 + i) * K + k0 + tx;
        Oh[o] = h; Ol[o] = l;
    }
}

__global__ void biascat(const float* __restrict__ bq, const float* __restrict__ bk,
                        const float* __restrict__ bv, float* __restrict__ o)
{
    const int i = blockIdx.x * 256 + threadIdx.x;
    float v = 0.f;
    if (i < 1024) v = bq[i];
    else if (i < 2048) v = bk[i - 1024];
    else if (i < 3072) v = bv[i - 2048];
    o[i] = v;
}

// ---------- fused attention: 512 threads, active-pair list, fast gelu ----------
#define ATT_T 512
__global__ __launch_bounds__(ATT_T, 1)
void attn_kernel(const float* __restrict__ c1, const float* __restrict__ cc,
                 const float* __restrict__ be1, const float* __restrict__ We2,
                 const float* __restrict__ be2,
                 float* __restrict__ attn_out, float* __restrict__ msg)
{
    const int b = blockIdx.x;
    extern __shared__ float sm[];
    float* sq  = sm;               // q
    float* sk  = sq  + NN * DD;    // k
    float* sv  = sk  + NN * DD;    // v
    float* sla = sv  + NN * DD;    // la + cc + be1 (folded)
    float* srb = sla + NN * DD;    // rb
    float* scb = srb + NN * DD;    // cc + be1 (1024)
    float* sw2 = scb + DD;         // We2 (1024)
    __shared__ float s_logits[49];
    __shared__ float s_attn[49];

    const int tid = threadIdx.x;
    const size_t rbase = (size_t)b * NN * 5120;

    for (int i = tid; i < DD; i += ATT_T) {
        scb[i] = cc[(size_t)b * DD + i] + be1[i];
        sw2[i] = We2[i];
    }
    __syncthreads();
    for (int i = tid; i < NN * DD; i += ATT_T) {
        const int n = i >> 10, d = i & 1023;
        const size_t ro = rbase + (size_t)n * 5120 + d;
        sq[i]  = c1[ro];
        sk[i]  = c1[ro + 1024];
        sv[i]  = c1[ro + 2048];
        sla[i] = c1[ro + 3072] + scb[d];     // fold cc+be1 into la
        srb[i] = c1[ro + 4096];
    }
    if (tid < 49) s_logits[tid] = -1e30f;    // masked pairs stay -inf
    __syncthreads();

    const int warp = tid >> 5, lane = tid & 31;
    const float be2v = be2[0];
    for (int pi = warp; pi < 41; pi += ATT_T / 32) {
        const int p = c_pairs[pi];
        const int n = p / 7, m = p % 7;
        const float* qn = sq  + n * DD;
        const float* km = sk  + m * DD;
        const float* ln = sla + n * DD;
        const float* rm = srb + m * DD;
        float aqk = 0.f, ae = 0.f;
        for (int d = lane; d < DD; d += 32) {
            aqk = fmaf(qn[d], km[d], aqk);
            ae  = fmaf(gelu_f(ln[d] + rm[d]), sw2[d], ae);
        }
#pragma unroll
        for (int o = 16; o; o >>= 1) {
            aqk += __shfl_xor_sync(0xffffffffu, aqk, o);
            ae  += __shfl_xor_sync(0xffffffffu, ae,  o);
        }
        if (lane == 0)
            s_logits[p] = aqk * (1.0f / 32.0f) + ae + be2v;
    }
    __syncthreads();

    if (tid < 7) {
        const int n = tid;
        float mx = -1e30f;
#pragma unroll
        for (int m = 0; m < 7; m++) mx = fmaxf(mx, s_logits[n * 7 + m]);
        float s = 0.f, e[7];
#pragma unroll
        for (int m = 0; m < 7; m++) {
            const float lg = s_logits[n * 7 + m];
            e[m] = (lg > -1e29f) ? expf(lg - mx) : 0.f;
            s += e[m];
        }
        const float inv = 1.0f / s;
#pragma unroll
        for (int m = 0; m < 7; m++) {
            const float a = e[m] * inv;
            s_attn[n * 7 + m] = a;
            attn_out[(size_t)b * 49 + n * 7 + m] = a;
        }
    }
    __syncthreads();

    const size_t obase = (size_t)b * NN * DD;
    for (int i = tid; i < NN * DD; i += ATT_T) {
        const int n = i >> 10, d = i & 1023;
        float s = 0.f;
#pragma unroll
        for (int m = 0; m < 7; m++) s = fmaf(s_attn[n * 7 + m], sv[m * DD + d], s);
        msg[obase + i] = s;
    }
}

__global__ void gq_copy_kernel(const float* __restrict__ upd, float* __restrict__ gq)
{
    const int idx = blockIdx.x * 256 + threadIdx.x;
    const int r = idx >> 10, d = idx & 1023, b = r / 7;
    gq[idx] = upd[(size_t)(b * 7 + 6) * 1024 + d];
}

// ---------- finalize ----------
__global__ void final_kernel(const float* __restrict__ upd, const float* __restrict__ h2,
                             const float* __restrict__ Wi2, const float* __restrict__ bi2,
                             float* __restrict__ out_fused, float* __restrict__ out_imp,
                             float* __restrict__ part)
{
    const int b = blockIdx.x;
    __shared__ float su[NN * DD];
    __shared__ float sf[DD];
    __shared__ float s_dot[49], s_implog[7], s_imp[8], s_dotf[7], s_fn2[1];

    const int tid = threadIdx.x, warp = tid >> 5, lane = tid & 31;
    const size_t base = (size_t)b * NN * DD;
    for (int i = tid; i < NN * DD; i += 256) su[i] = upd[base + i];
    __syncthreads();

    for (int p = warp; p < 49; p += 8) {
        const int n = p / 7, m = p % 7;
        float s = 0.f;
        for (int d = lane; d < DD; d += 32) s = fmaf(su[n * DD + d], su[m * DD + d], s);
#pragma unroll
        for (int o = 16; o; o >>= 1) s += __shfl_xor_sync(0xffffffffu, s, o);
        if (lane == 0) s_dot[p] = s;
    }
    if (warp < 7) {
        float s = 0.f;
        for (int d = lane; d < DD; d += 32) s = fmaf(h2[base + warp * DD + d], Wi2[d], s);
#pragma unroll
        for (int o = 16; o; o >>= 1) s += __shfl_xor_sync(0xffffffffu, s, o);
        if (lane == 0) s_implog[warp] = s + bi2[0];
    }
    __syncthreads();

    if (tid == 0) {
        float mx = -1e30f;
#pragma unroll
        for (int n = 0; n < 7; n++) mx = fmaxf(mx, s_implog[n]);
        float e[7], sum = 0.f;
#pragma unroll
        for (int n = 0; n < 7; n++) { e[n] = expf(s_implog[n] - mx); sum += e[n]; }
        float imp[7];
#pragma unroll
        for (int n = 0; n < 7; n++) imp[n] = e[n] / sum;
        const float cap[7] = {1.f,1.f,1.f,0.26f,1.f,1.f,0.24f};
        const float fre[7] = {1.f,1.f,1.f,0.f,1.f,1.f,0.f};
        float capped[7], csum = 0.f, fmass = 0.f;
#pragma unroll
        for (int n = 0; n < 7; n++) {
            capped[n] = fminf(imp[n], cap[n]);
            csum += capped[n]; fmass += imp[n] * fre[n];
        }
        const float residual = fmaxf(1.0f - csum, 0.0f);
        float redis[7], rsum = 0.f;
#pragma unroll
        for (int n = 0; n < 7; n++) {
            const float fs = (fmass > 1e-6f) ? imp[n] * fre[n] / fmaxf(fmass, 1e-6f)
                                             : fre[n] * 0.2f;
            redis[n] = capped[n] + fs * residual;
            rsum += redis[n];
        }
        const float inv = 1.0f / fmaxf(rsum, 1e-6f);
#pragma unroll
        for (int n = 0; n < 7; n++) { s_imp[n] = redis[n] * inv; out_imp[b * 7 + n] = s_imp[n]; }
    }
    __syncthreads();

    for (int d = tid; d < DD; d += 256) {
        float f = 0.f;
#pragma unroll
        for (int n = 0; n < 7; n++) f = fmaf(s_imp[n], su[n * DD + d], f);
        sf[d] = f;
        out_fused[(size_t)b * DD + d] = f;
    }
    __syncthreads();

    if (warp < 7) {
        float s = 0.f;
        for (int d = lane; d < DD; d += 32) s = fmaf(su[warp * DD + d], sf[d], s);
#pragma unroll
        for (int o = 16; o; o >>= 1) s += __shfl_xor_sync(0xffffffffu, s, o);
        if (lane == 0) s_dotf[warp] = s;
    } else if (warp == 7) {
        float s = 0.f;
        for (int d = lane; d < DD; d += 32) s = fmaf(sf[d], sf[d], s);
#pragma unroll
        for (int o = 16; o; o >>= 1) s += __shfl_xor_sync(0xffffffffu, s, o);
        if (lane == 0) s_fn2[0] = s;
    }
    __syncthreads();

    if (tid == 0) {
        float norm[7];
#pragma unroll
        for (int n = 0; n < 7; n++) norm[n] = sqrtf(s_dot[n * 7 + n]);
        const float fnorm = sqrtf(s_fn2[0]);
        float edge = 0.f, non = 0.f, align = 0.f;
#pragma unroll
        for (int n = 0; n < 7; n++) {
#pragma unroll
            for (int m = 0; m < 7; m++) {
                const float cosv = s_dot[n * 7 + m] / fmaxf(norm[n] * norm[m], 1e-8f);
                const float adj = c_adj[n * 7 + m];
                edge += (1.0f - cosv) * adj;
                if (n != m) non += fmaxf(cosv - 0.35f, 0.0f) * (1.0f - adj);
            }
            align += 1.0f - s_dotf[n] / (fmaxf(norm[n], 1e-12f) * fmaxf(fnorm, 1e-12f));
        }
        part[b * 3 + 0] = edge; part[b * 3 + 1] = non; part[b * 3 + 2] = align;
    }
}

__global__ void loss_reduce_kernel(const float* __restrict__ part, float* __restrict__ out)
{
    __shared__ float se[256], sn[256], sa[256];
    const int t = threadIdx.x;
    float e = 0.f, n = 0.f, a = 0.f;
    for (int i = t; i < BSZ; i += 256) {
        e += part[i * 3 + 0]; n += part[i * 3 + 1]; a += part[i * 3 + 2];
    }
    se[t] = e; sn[t] = n; sa[t] = a;
    __syncthreads();
    for (int s = 128; s; s >>= 1) {
        if (t < s) { se[t] += se[t+s]; sn[t] += sn[t+s]; sa[t] += sa[t+s]; }
        __syncthreads();
    }
    if (t == 0) {
        out[OFF_PHYS]  = se[0] / 41.0f + 0.5f * (sn[0] / 8.0f);
        out[OFF_ALIGN] = sa[0] / 7168.0f;
    }
}

// ---------- host ----------
extern "C" void kernel_launch(void* const* d_in, const int* in_sizes, int n_in,
                              void* d_out, int out_size)
{
    (void)in_sizes; (void)n_in; (void)out_size;
    const float* nodes = (const float*)d_in[0];
    const float* Wq  = (const float*)d_in[1];  const float* bq  = (const float*)d_in[2];
    const float* Wk  = (const float*)d_in[3];  const float* bk  = (const float*)d_in[4];
    const float* Wv  = (const float*)d_in[5];  const float* bv  = (const float*)d_in[6];
    const float* We1 = (const float*)d_in[7];  const float* be1 = (const float*)d_in[8];
    const float* We2 = (const float*)d_in[9];  const float* be2 = (const float*)d_in[10];
    const float* Wu1 = (const float*)d_in[11]; const float* bu1 = (const float*)d_in[12];
    const float* Wu2 = (const float*)d_in[13]; const float* bu2 = (const float*)d_in[14];
    const float* Wi1 = (const float*)d_in[15]; const float* bi1 = (const float*)d_in[16];
    const float* Wi2 = (const float*)d_in[17]; const float* bi2 = (const float*)d_in[18];
    float* out = (float*)d_out;

    uint16_t *w5h, *w5l, *wech, *wecl, *wu1h, *wu1l, *wu2h, *wu2l, *wi1h, *wi1l;
    float *c1, *cc, *msg, *h1, *h2, *gq, *b5, *part;
    cudaGetSymbolAddress((void**)&w5h,  g_w5h);
    cudaGetSymbolAddress((void**)&w5l,  g_w5l);
    cudaGetSymbolAddress((void**)&wech, g_wech);
    cudaGetSymbolAddress((void**)&wecl, g_wecl);
    cudaGetSymbolAddress((void**)&wu1h, g_wu1h);
    cudaGetSymbolAddress((void**)&wu1l, g_wu1l);
    cudaGetSymbolAddress((void**)&wu2h, g_wu2h);
    cudaGetSymbolAddress((void**)&wu2l, g_wu2l);
    cudaGetSymbolAddress((void**)&wi1h, g_wi1h);
    cudaGetSymbolAddress((void**)&wi1l, g_wi1l);
    cudaGetSymbolAddress((void**)&c1,   g_c1);
    cudaGetSymbolAddress((void**)&cc,   g_cc);
    cudaGetSymbolAddress((void**)&msg,  g_msg);
    cudaGetSymbolAddress((void**)&h1,   g_h1);
    cudaGetSymbolAddress((void**)&h2,   g_h2);
    cudaGetSymbolAddress((void**)&gq,   g_gq);
    cudaGetSymbolAddress((void**)&b5,   g_b5);
    cudaGetSymbolAddress((void**)&part, g_part);

    const int SMEMG = 2 * STAGEH * (int)sizeof(uint16_t);
    cudaFuncSetAttribute(gemm_bfs, cudaFuncAttributeMaxDynamicSharedMemorySize, SMEMG);
    const int attn_smem = (5 * NN * DD + 2 * DD) * (int)sizeof(float);   // 151552
    cudaFuncSetAttribute(attn_kernel, cudaFuncAttributeMaxDynamicSharedMemorySize, attn_smem);

    const dim3 blk(256);
    const dim3 tg(32, 32), tg2(64, 32);
    const int M1 = 1024 * 1024;
    transpose_split<<<tg,  blk>>>(Wq,           w5h,          w5l,          1024);
    transpose_split<<<tg,  blk>>>(Wk,           w5h + M1,     w5l + M1,     1024);
    transpose_split<<<tg,  blk>>>(Wv,           w5h + 2 * M1, w5l + 2 * M1, 1024);
    transpose_split<<<tg,  blk>>>(We1,          w5h + 3 * M1, w5l + 3 * M1, 1024);
    transpose_split<<<tg,  blk>>>(We1 + M1,     w5h + 4 * M1, w5l + 4 * M1, 1024);
    transpose_split<<<tg,  blk>>>(We1 + 2 * M1, wech,         wecl,         1024);
    transpose_split<<<tg2, blk>>>(Wu1,          wu1h,         wu1l,         2048);
    transpose_split<<<tg,  blk>>>(Wu2,          wu2h,         wu2l,         1024);
    transpose_split<<<tg2, blk>>>(Wi1,          wi1h,         wi1l,         2048);
    biascat<<<20, blk>>>(bq, bk, bv, b5);

    const int BIGK = 1 << 30;
    gemm_bfs<<<dim3(40, 56), blk, SMEMG>>>(nodes, 1024, nullptr, 0, BIGK,
                                           w5h, w5l, b5, nullptr, c1, 5120, 1024, 0);
    gemm_bfs<<<dim3(8, 8), blk, SMEMG>>>(nodes + 6 * 1024, 7168, nullptr, 0, BIGK,
                                         wech, wecl, nullptr, nullptr, cc, 1024, 1024, 0);
    attn_kernel<<<BSZ, dim3(ATT_T), attn_smem>>>(c1, cc, be1, We2, be2, out + OFF_ATTN, msg);
    gemm_bfs<<<dim3(8, 56), blk, SMEMG>>>(nodes, 1024, msg, 1024, 1024,
                                          wu1h, wu1l, bu1, nullptr, h1, 1024, 2048, 1);
    gemm_bfs<<<dim3(8, 56), blk, SMEMG>>>(h1, 1024, nullptr, 0, BIGK,
                                          wu2h, wu2l, bu2, nodes, out + OFF_UPD, 1024, 1024, 2);
    gq_copy_kernel<<<(MR * DD) / 256, blk>>>(out + OFF_UPD, gq);
    gemm_bfs<<<dim3(8, 56), blk, SMEMG>>>(out + OFF_UPD, 1024, gq, 1024, 1024,
                                          wi1h, wi1l, bi1, nullptr, h2, 1024, 2048, 1);
    final_kernel<<<BSZ, blk>>>(out + OFF_UPD, h2, Wi2, bi2, out, out + OFF_IMP, part);
    loss_reduce_kernel<<<1, blk>>>(part, out);
}

// round 13
// speedup vs baseline: 3.6585x; 1.6453x over previous
#include <cuda_runtime.h>
#include <cuda_fp16.h>
#include <math.h>
#include <stdint.h>

#define BSZ 1024
#define NN  7
#define DD  1024
#define MR  (BSZ*NN)

#define OFF_UPD   (BSZ*DD)
#define OFF_IMP   (OFF_UPD + BSZ*NN*DD)
#define OFF_ATTN  (OFF_IMP + BSZ*NN)
#define OFF_PHYS  (OFF_ATTN + BSZ*NN*NN)
#define OFF_ALIGN (OFF_PHYS + 1)

// ---------- scratch ----------
__device__ uint16_t g_w5 [5*1024*1024];   // [Wq|Wk|Wv|Wea|Web]^T fp16, [N=5120][K=1024]
__device__ uint16_t g_wec[1024*1024];
__device__ uint16_t g_wu1[1024*2048];
__device__ uint16_t g_wu2[1024*1024];
__device__ uint16_t g_wi1[1024*2048];
__device__ float g_c1  [MR*5120];
__device__ float g_cc  [BSZ*DD];
__device__ float g_msg [MR*DD];
__device__ float g_h1  [MR*DD];
__device__ float g_h2  [MR*DD];
__device__ float g_gq  [MR*DD];
__device__ float g_b5  [5120];
__device__ float g_part[BSZ*3];

__constant__ float c_adj[49] = {
    1,1,0,0,1,1,1, 1,1,1,1,1,1,1, 0,1,1,0,1,0,1, 0,1,0,1,1,1,1,
    1,1,1,1,1,1,1, 1,1,0,1,1,1,1, 1,1,1,1,1,1,1};
__constant__ int c_pairs[41] = {
    0,1,4,5,6,
    7,8,9,10,11,12,13,
    15,16,18,20,
    22,24,25,26,27,
    28,29,30,31,32,33,34,
    35,36,38,39,40,41,
    42,43,44,45,46,47,48};

__device__ __forceinline__ float gelu_f(float x) {
    const float x2 = x * x;
    const float u = x * fmaf(0.0356774081f, x2, 0.7978845608f);
    float t;
    asm("tanh.approx.f32 %0, %1;" : "=f"(t) : "f"(u));
    const float hx = 0.5f * x;
    return fmaf(hx, t, hx);
}
__device__ __forceinline__ void mma_f16(float* c, const uint32_t* a, const uint32_t* b) {
    asm volatile(
        "mma.sync.aligned.m16n8k16.row.col.f32.f16.f16.f32 "
        "{%0,%1,%2,%3}, {%4,%5,%6,%7}, {%8,%9}, {%0,%1,%2,%3};"
        : "+f"(c[0]), "+f"(c[1]), "+f"(c[2]), "+f"(c[3])
        : "r"(a[0]), "r"(a[1]), "r"(a[2]), "r"(a[3]), "r"(b[0]), "r"(b[1]));
}

// ---------- fp16 single-pass tensor-core GEMM ----------
// C[M,Ncols] = concatA[M,K](fp32->fp16) @ Bt[Ncols,K](fp16)^T
// 128x128 tile, BK=32, 2-stage smem double buffer, 8 warps (4x2), warp tile 32x64
#define SH   40                   // halves per smem row
#define MATH (128*SH)             // halves per matrix (A or B) per stage
#define STAGEH (2*MATH)

__global__ __launch_bounds__(256, 1)
void gemm_f16(const float* __restrict__ A0, int lda0,
              const float* __restrict__ A1, int lda1, int ksplit,
              const uint16_t* __restrict__ Bt,
              const float* __restrict__ bias, const float* __restrict__ Rres,
              float* __restrict__ C, int ldc, int K, int epi)
{
    extern __shared__ __align__(16) uint16_t sh[];
    const int tid = threadIdx.x, wid = tid >> 5, lane = tid & 31;
    const int m0 = blockIdx.y * 128, n0 = blockIdx.x * 128;
    const int NC = K / 32;
    const int wm = wid & 3, wn = wid >> 2;
    const int gid = lane >> 2, tig = lane & 3;

    const int lrow = tid >> 1;            // 0..127
    const int kb0  = (tid & 1) * 16;      // halves: 0 or 16

    float acc[2][8][4];
#pragma unroll
    for (int i = 0; i < 2; i++)
#pragma unroll
        for (int j = 0; j < 8; j++)
#pragma unroll
            for (int q = 0; q < 4; q++) acc[i][j][q] = 0.f;

    float4 ra[4];
    uint4  rb16[2];

#define LOADG(c) do { \
    const int _k0 = (c) * 32; \
    const float* _ap; \
    if (_k0 < ksplit) _ap = A0 + (size_t)(m0 + lrow) * lda0 + _k0; \
    else              _ap = A1 + (size_t)(m0 + lrow) * lda1 + (_k0 - ksplit); \
    _Pragma("unroll") \
    for (int _j = 0; _j < 4; _j++) ra[_j] = *(const float4*)(_ap + kb0 + 4 * _j); \
    const size_t _bo = (size_t)(n0 + lrow) * K + _k0 + kb0; \
    rb16[0] = *(const uint4*)(Bt + _bo); \
    rb16[1] = *(const uint4*)(Bt + _bo + 8); \
} while (0)

#define STS_STAGE(st) do { \
    uint16_t* _base = sh + (st) * STAGEH; \
    uint16_t _h[16]; \
    _Pragma("unroll") \
    for (int _j = 0; _j < 4; _j++) { \
        _h[4*_j+0] = __half_as_ushort(__float2half_rn(ra[_j].x)); \
        _h[4*_j+1] = __half_as_ushort(__float2half_rn(ra[_j].y)); \
        _h[4*_j+2] = __half_as_ushort(__float2half_rn(ra[_j].z)); \
        _h[4*_j+3] = __half_as_ushort(__float2half_rn(ra[_j].w)); \
    } \
    const int _off = lrow * SH + kb0; \
    *(uint4*)(_base + _off)            = *(uint4*)&_h[0]; \
    *(uint4*)(_base + _off + 8)        = *(uint4*)&_h[8]; \
    *(uint4*)(_base + MATH + _off)     = rb16[0]; \
    *(uint4*)(_base + MATH + _off + 8) = rb16[1]; \
} while (0)

    LOADG(0);
    STS_STAGE(0);
    __syncthreads();

    for (int c = 0; c < NC; c++) {
        if (c + 1 < NC) LOADG(c + 1);

        const uint16_t* sa = sh + (c & 1) * STAGEH;
        const uint16_t* sb = sa + MATH;
#pragma unroll
        for (int ks = 0; ks < 2; ks++) {
            const int kk = ks * 16 + 2 * tig;
            uint32_t aF[2][4], bF[8][2];
#pragma unroll
            for (int mt = 0; mt < 2; mt++) {
                const int rb = (wm * 32 + mt * 16 + gid) * SH + kk;
                aF[mt][0] = *(const uint32_t*)(sa + rb);
                aF[mt][1] = *(const uint32_t*)(sa + rb + 8 * SH);
                aF[mt][2] = *(const uint32_t*)(sa + rb + 8);
                aF[mt][3] = *(const uint32_t*)(sa + rb + 8 * SH + 8);
            }
#pragma unroll
            for (int nt = 0; nt < 8; nt++) {
                const int nr = (wn * 64 + nt * 8 + gid) * SH + kk;
                bF[nt][0] = *(const uint32_t*)(sb + nr);
                bF[nt][1] = *(const uint32_t*)(sb + nr + 8);
            }
#pragma unroll
            for (int mt = 0; mt < 2; mt++)
#pragma unroll
                for (int nt = 0; nt < 8; nt++)
                    mma_f16(acc[mt][nt], aF[mt], bF[nt]);
        }

        if (c + 1 < NC) STS_STAGE((c + 1) & 1);
        __syncthreads();
    }

#pragma unroll
    for (int mt = 0; mt < 2; mt++) {
#pragma unroll
        for (int rr = 0; rr < 2; rr++) {
            const int row = m0 + wm * 32 + mt * 16 + gid + rr * 8;
#pragma unroll
            for (int nt = 0; nt < 8; nt++) {
                const int col = n0 + wn * 64 + nt * 8 + tig * 2;
                float v0 = acc[mt][nt][rr * 2 + 0];
                float v1 = acc[mt][nt][rr * 2 + 1];
                if (bias) { v0 += bias[col]; v1 += bias[col + 1]; }
                if (epi == 1) { v0 = gelu_f(v0); v1 = gelu_f(v1); }
                else if (epi == 2) {
                    const float2 rv = *(const float2*)(Rres + (size_t)row * 1024 + col);
                    v0 += rv.x; v1 += rv.y;
                }
                *(float2*)(C + (size_t)row * ldc + col) = make_float2(v0, v1);
            }
        }
    }
}

// ---------- unified prep: all weight transposes (fp32 -> fp16, K-major) + bias concat ----------
// blocks 0..11263: 32x32 transpose tiles; blocks 11264..11283: bias concat
__global__ void prep_all(const float* __restrict__ Wq, const float* __restrict__ Wk,
                         const float* __restrict__ Wv, const float* __restrict__ We1,
                         const float* __restrict__ Wu1, const float* __restrict__ Wu2,
                         const float* __restrict__ Wi1,
                         const float* __restrict__ bq, const float* __restrict__ bk,
                         const float* __restrict__ bv,
                         uint16_t* __restrict__ w5, uint16_t* __restrict__ wec,
                         uint16_t* __restrict__ wu1, uint16_t* __restrict__ wu2,
                         uint16_t* __restrict__ wi1, float* __restrict__ b5)
{
    const int bid = blockIdx.x;
    if (bid >= 11264) {
        const int i = (bid - 11264) * 256 + threadIdx.x;
        if (i < 5120) {
            float v = 0.f;
            if (i < 1024) v = bq[i];
            else if (i < 2048) v = bk[i - 1024];
            else if (i < 3072) v = bv[i - 2048];
            b5[i] = v;
        }
        return;
    }
    const float* src; uint16_t* dst; int K, t;
    if (bid < 5120) {
        const int wsel = bid >> 10; t = bid & 1023;
        src = (wsel == 0) ? Wq : (wsel == 1) ? Wk : (wsel == 2) ? Wv
            : (wsel == 3) ? We1 : (We1 + 1024 * 1024);
        dst = w5 + (size_t)wsel * 1024 * 1024; K = 1024;
    } else if (bid < 6144) { src = We1 + 2 * 1024 * 1024; dst = wec; K = 1024; t = bid - 5120; }
    else if (bid < 8192)  { src = Wu1; dst = wu1; K = 2048; t = bid - 6144; }
    else if (bid < 9216)  { src = Wu2; dst = wu2; K = 1024; t = bid - 8192; }
    else                  { src = Wi1; dst = wi1; K = 2048; t = bid - 9216; }

    const int ktiles = K >> 5;
    const int k0 = (t % ktiles) * 32, n0 = (t / ktiles) * 32;
    __shared__ float tt[32][33];
    const int tx = threadIdx.x & 31, ty = threadIdx.x >> 5;
    for (int i = ty; i < 32; i += 8) tt[i][tx] = src[(size_t)(k0 + i) * 1024 + n0 + tx];
    __syncthreads();
    for (int i = ty; i < 32; i += 8)
        dst[(size_t)(n0 + i) * K + k0 + tx] = __half_as_ushort(__float2half_rn(tt[tx][i]));
}

// ---------- fused attention (unchanged from R11) ----------
#define ATT_T 512
__global__ __launch_bounds__(ATT_T, 1)
void attn_kernel(const float* __restrict__ c1, const float* __restrict__ cc,
                 const float* __restrict__ be1, const float* __restrict__ We2,
                 const float* __restrict__ be2,
                 float* __restrict__ attn_out, float* __restrict__ msg)
{
    const int b = blockIdx.x;
    extern __shared__ float sm[];
    float* sq  = sm;
    float* sk  = sq  + NN * DD;
    float* sv  = sk  + NN * DD;
    float* sla = sv  + NN * DD;
    float* srb = sla + NN * DD;
    float* scb = srb + NN * DD;
    float* sw2 = scb + DD;
    __shared__ float s_logits[49];
    __shared__ float s_attn[49];

    const int tid = threadIdx.x;
    const size_t rbase = (size_t)b * NN * 5120;

    for (int i = tid; i < DD; i += ATT_T) {
        scb[i] = cc[(size_t)b * DD + i] + be1[i];
        sw2[i] = We2[i];
    }
    __syncthreads();
    for (int i = tid; i < NN * DD; i += ATT_T) {
        const int n = i >> 10, d = i & 1023;
        const size_t ro = rbase + (size_t)n * 5120 + d;
        sq[i]  = c1[ro];
        sk[i]  = c1[ro + 1024];
        sv[i]  = c1[ro + 2048];
        sla[i] = c1[ro + 3072] + scb[d];
        srb[i] = c1[ro + 4096];
    }
    if (tid < 49) s_logits[tid] = -1e30f;
    __syncthreads();

    const int warp = tid >> 5, lane = tid & 31;
    const float be2v = be2[0];
    for (int pi = warp; pi < 41; pi += ATT_T / 32) {
        const int p = c_pairs[pi];
        const int n = p / 7, m = p % 7;
        const float* qn = sq  + n * DD;
        const float* km = sk  + m * DD;
        const float* ln = sla + n * DD;
        const float* rm = srb + m * DD;
        float aqk = 0.f, ae = 0.f;
        for (int d = lane; d < DD; d += 32) {
            aqk = fmaf(qn[d], km[d], aqk);
            ae  = fmaf(gelu_f(ln[d] + rm[d]), sw2[d], ae);
        }
#pragma unroll
        for (int o = 16; o; o >>= 1) {
            aqk += __shfl_xor_sync(0xffffffffu, aqk, o);
            ae  += __shfl_xor_sync(0xffffffffu, ae,  o);
        }
        if (lane == 0)
            s_logits[p] = aqk * (1.0f / 32.0f) + ae + be2v;
    }
    __syncthreads();

    if (tid < 7) {
        const int n = tid;
        float mx = -1e30f;
#pragma unroll
        for (int m = 0; m < 7; m++) mx = fmaxf(mx, s_logits[n * 7 + m]);
        float s = 0.f, e[7];
#pragma unroll
        for (int m = 0; m < 7; m++) {
            const float lg = s_logits[n * 7 + m];
            e[m] = (lg > -1e29f) ? expf(lg - mx) : 0.f;
            s += e[m];
        }
        const float inv = 1.0f / s;
#pragma unroll
        for (int m = 0; m < 7; m++) {
            const float a = e[m] * inv;
            s_attn[n * 7 + m] = a;
            attn_out[(size_t)b * 49 + n * 7 + m] = a;
        }
    }
    __syncthreads();

    const size_t obase = (size_t)b * NN * DD;
    for (int i = tid; i < NN * DD; i += ATT_T) {
        const int n = i >> 10, d = i & 1023;
        float s = 0.f;
#pragma unroll
        for (int m = 0; m < 7; m++) s = fmaf(s_attn[n * 7 + m], sv[m * DD + d], s);
        msg[obase + i] = s;
    }
}

__global__ void gq_copy_kernel(const float* __restrict__ upd, float* __restrict__ gq)
{
    const int idx = blockIdx.x * 256 + threadIdx.x;
    const int r = idx >> 10, d = idx & 1023, b = r / 7;
    gq[idx] = upd[(size_t)(b * 7 + 6) * 1024 + d];
}

// ---------- finalize (unchanged) ----------
__global__ void final_kernel(const float* __restrict__ upd, const float* __restrict__ h2,
                             const float* __restrict__ Wi2, const float* __restrict__ bi2,
                             float* __restrict__ out_fused, float* __restrict__ out_imp,
                             float* __restrict__ part)
{
    const int b = blockIdx.x;
    __shared__ float su[NN * DD];
    __shared__ float sf[DD];
    __shared__ float s_dot[49], s_implog[7], s_imp[8], s_dotf[7], s_fn2[1];

    const int tid = threadIdx.x, warp = tid >> 5, lane = tid & 31;
    const size_t base = (size_t)b * NN * DD;
    for (int i = tid; i < NN * DD; i += 256) su[i] = upd[base + i];
    __syncthreads();

    for (int p = warp; p < 49; p += 8) {
        const int n = p / 7, m = p % 7;
        float s = 0.f;
        for (int d = lane; d < DD; d += 32) s = fmaf(su[n * DD + d], su[m * DD + d], s);
#pragma unroll
        for (int o = 16; o; o >>= 1) s += __shfl_xor_sync(0xffffffffu, s, o);
        if (lane == 0) s_dot[p] = s;
    }
    if (warp < 7) {
        float s = 0.f;
        for (int d = lane; d < DD; d += 32) s = fmaf(h2[base + warp * DD + d], Wi2[d], s);
#pragma unroll
        for (int o = 16; o; o >>= 1) s += __shfl_xor_sync(0xffffffffu, s, o);
        if (lane == 0) s_implog[warp] = s + bi2[0];
    }
    __syncthreads();

    if (tid == 0) {
        float mx = -1e30f;
#pragma unroll
        for (int n = 0; n < 7; n++) mx = fmaxf(mx, s_implog[n]);
        float e[7], sum = 0.f;
#pragma unroll
        for (int n = 0; n < 7; n++) { e[n] = expf(s_implog[n] - mx); sum += e[n]; }
        float imp[7];
#pragma unroll
        for (int n = 0; n < 7; n++) imp[n] = e[n] / sum;
        const float cap[7] = {1.f,1.f,1.f,0.26f,1.f,1.f,0.24f};
        const float fre[7] = {1.f,1.f,1.f,0.f,1.f,1.f,0.f};
        float capped[7], csum = 0.f, fmass = 0.f;
#pragma unroll
        for (int n = 0; n < 7; n++) {
            capped[n] = fminf(imp[n], cap[n]);
            csum += capped[n]; fmass += imp[n] * fre[n];
        }
        const float residual = fmaxf(1.0f - csum, 0.0f);
        float redis[7], rsum = 0.f;
#pragma unroll
        for (int n = 0; n < 7; n++) {
            const float fs = (fmass > 1e-6f) ? imp[n] * fre[n] / fmaxf(fmass, 1e-6f)
                                             : fre[n] * 0.2f;
            redis[n] = capped[n] + fs * residual;
            rsum += redis[n];
        }
        const float inv = 1.0f / fmaxf(rsum, 1e-6f);
#pragma unroll
        for (int n = 0; n < 7; n++) { s_imp[n] = redis[n] * inv; out_imp[b * 7 + n] = s_imp[n]; }
    }
    __syncthreads();

    for (int d = tid; d < DD; d += 256) {
        float f = 0.f;
#pragma unroll
        for (int n = 0; n < 7; n++) f = fmaf(s_imp[n], su[n * DD + d], f);
        sf[d] = f;
        out_fused[(size_t)b * DD + d] = f;
    }
    __syncthreads();

    if (warp < 7) {
        float s = 0.f;
        for (int d = lane; d < DD; d += 32) s = fmaf(su[warp * DD + d], sf[d], s);
#pragma unroll
        for (int o = 16; o; o >>= 1) s += __shfl_xor_sync(0xffffffffu, s, o);
        if (lane == 0) s_dotf[warp] = s;
    } else if (warp == 7) {
        float s = 0.f;
        for (int d = lane; d < DD; d += 32) s = fmaf(sf[d], sf[d], s);
#pragma unroll
        for (int o = 16; o; o >>= 1) s += __shfl_xor_sync(0xffffffffu, s, o);
        if (lane == 0) s_fn2[0] = s;
    }
    __syncthreads();

    if (tid == 0) {
        float norm[7];
#pragma unroll
        for (int n = 0; n < 7; n++) norm[n] = sqrtf(s_dot[n * 7 + n]);
        const float fnorm = sqrtf(s_fn2[0]);
        float edge = 0.f, non = 0.f, align = 0.f;
#pragma unroll
        for (int n = 0; n < 7; n++) {
#pragma unroll
            for (int m = 0; m < 7; m++) {
                const float cosv = s_dot[n * 7 + m] / fmaxf(norm[n] * norm[m], 1e-8f);
                const float adj = c_adj[n * 7 + m];
                edge += (1.0f - cosv) * adj;
                if (n != m) non += fmaxf(cosv - 0.35f, 0.0f) * (1.0f - adj);
            }
            align += 1.0f - s_dotf[n] / (fmaxf(norm[n], 1e-12f) * fmaxf(fnorm, 1e-12f));
        }
        part[b * 3 + 0] = edge; part[b * 3 + 1] = non; part[b * 3 + 2] = align;
    }
}

__global__ void loss_reduce_kernel(const float* __restrict__ part, float* __restrict__ out)
{
    __shared__ float se[256], sn[256], sa[256];
    const int t = threadIdx.x;
    float e = 0.f, n = 0.f, a = 0.f;
    for (int i = t; i < BSZ; i += 256) {
        e += part[i * 3 + 0]; n += part[i * 3 + 1]; a += part[i * 3 + 2];
    }
    se[t] = e; sn[t] = n; sa[t] = a;
    __syncthreads();
    for (int s = 128; s; s >>= 1) {
        if (t < s) { se[t] += se[t+s]; sn[t] += sn[t+s]; sa[t] += sa[t+s]; }
        __syncthreads();
    }
    if (t == 0) {
        out[OFF_PHYS]  = se[0] / 41.0f + 0.5f * (sn[0] / 8.0f);
        out[OFF_ALIGN] = sa[0] / 7168.0f;
    }
}

// ---------- host ----------
extern "C" void kernel_launch(void* const* d_in, const int* in_sizes, int n_in,
                              void* d_out, int out_size)
{
    (void)in_sizes; (void)n_in; (void)out_size;
    const float* nodes = (const float*)d_in[0];
    const float* Wq  = (const float*)d_in[1];  const float* bq  = (const float*)d_in[2];
    const float* Wk  = (const float*)d_in[3];  const float* bk  = (const float*)d_in[4];
    const float* Wv  = (const float*)d_in[5];  const float* bv  = (const float*)d_in[6];
    const float* We1 = (const float*)d_in[7];  const float* be1 = (const float*)d_in[8];
    const float* We2 = (const float*)d_in[9];  const float* be2 = (const float*)d_in[10];
    const float* Wu1 = (const float*)d_in[11]; const float* bu1 = (const float*)d_in[12];
    const float* Wu2 = (const float*)d_in[13]; const float* bu2 = (const float*)d_in[14];
    const float* Wi1 = (const float*)d_in[15]; const float* bi1 = (const float*)d_in[16];
    const float* Wi2 = (const float*)d_in[17]; const float* bi2 = (const float*)d_in[18];
    float* out = (float*)d_out;

    uint16_t *w5, *wec, *wu1, *wu2, *wi1;
    float *c1, *cc, *msg, *h1, *h2, *gq, *b5, *part;
    cudaGetSymbolAddress((void**)&w5,  g_w5);
    cudaGetSymbolAddress((void**)&wec, g_wec);
    cudaGetSymbolAddress((void**)&wu1, g_wu1);
    cudaGetSymbolAddress((void**)&wu2, g_wu2);
    cudaGetSymbolAddress((void**)&wi1, g_wi1);
    cudaGetSymbolAddress((void**)&c1,  g_c1);
    cudaGetSymbolAddress((void**)&cc,  g_cc);
    cudaGetSymbolAddress((void**)&msg, g_msg);
    cudaGetSymbolAddress((void**)&h1,  g_h1);
    cudaGetSymbolAddress((void**)&h2,  g_h2);
    cudaGetSymbolAddress((void**)&gq,  g_gq);
    cudaGetSymbolAddress((void**)&b5,  g_b5);
    cudaGetSymbolAddress((void**)&part, g_part);

    const int SMEMG = 2 * STAGEH * (int)sizeof(uint16_t);   // 40960
    cudaFuncSetAttribute(gemm_f16, cudaFuncAttributeMaxDynamicSharedMemorySize, SMEMG);
    const int attn_smem = (5 * NN * DD + 2 * DD) * (int)sizeof(float);
    cudaFuncSetAttribute(attn_kernel, cudaFuncAttributeMaxDynamicSharedMemorySize, attn_smem);

    const dim3 blk(256);
    // launch 1: all weight prep in ONE kernel
    prep_all<<<11284, blk>>>(Wq, Wk, Wv, We1, Wu1, Wu2, Wi1, bq, bk, bv,
                             w5, wec, wu1, wu2, wi1, b5);

    const int BIGK = 1 << 30;
    // launch 2: C1[7168,5120] = nodes @ [Wq|Wk|Wv|Wea|Web]
    gemm_f16<<<dim3(40, 56), blk, SMEMG>>>(nodes, 1024, nullptr, 0, BIGK,
                                           w5, b5, nullptr, c1, 5120, 1024, 0);
    // launch 3: cc = nodes[:,-1] @ Wec
    gemm_f16<<<dim3(8, 8), blk, SMEMG>>>(nodes + 6 * 1024, 7168, nullptr, 0, BIGK,
                                         wec, nullptr, nullptr, cc, 1024, 1024, 0);
    // launch 4: attention
    attn_kernel<<<BSZ, dim3(ATT_T), attn_smem>>>(c1, cc, be1, We2, be2, out + OFF_ATTN, msg);
    // launch 5: h1 = gelu(cat(nodes,msg) @ Wu1 + bu1)
    gemm_f16<<<dim3(8, 56), blk, SMEMG>>>(nodes, 1024, msg, 1024, 1024,
                                          wu1, bu1, nullptr, h1, 1024, 2048, 1);
    // launch 6 (ncu capture target): updated = h1 @ Wu2 + bu2 + nodes
    gemm_f16<<<dim3(8, 56), blk, SMEMG>>>(h1, 1024, nullptr, 0, BIGK,
                                          wu2, bu2, nodes, out + OFF_UPD, 1024, 1024, 2);
    // launch 7
    gq_copy_kernel<<<(MR * DD) / 256, blk>>>(out + OFF_UPD, gq);
    // launch 8: h2 = gelu(cat(updated,gq) @ Wi1 + bi1)
    gemm_f16<<<dim3(8, 56), blk, SMEMG>>>(out + OFF_UPD, 1024, gq, 1024, 1024,
                                          wi1, bi1, nullptr, h2, 1024, 2048, 1);
    // launch 9, 10
    final_kernel<<<BSZ, blk>>>(out + OFF_UPD, h2, Wi2, bi2, out, out + OFF_IMP, part);
    loss_reduce_kernel<<<1, blk>>>(part, out);
}

// round 15
// speedup vs baseline: 4.7347x; 1.2942x over previous
#include <cuda_runtime.h>
#include <cuda_fp16.h>
#include <math.h>
#include <stdint.h>

#define BSZ 1024
#define NN  7
#define DD  1024
#define MR  (BSZ*NN)

#define OFF_UPD   (BSZ*DD)
#define OFF_IMP   (OFF_UPD + BSZ*NN*DD)
#define OFF_ATTN  (OFF_IMP + BSZ*NN)
#define OFF_PHYS  (OFF_ATTN + BSZ*NN*NN)
#define OFF_ALIGN (OFF_PHYS + 1)

// ---------- scratch ----------
__device__ uint16_t g_w5 [5*1024*1024];
__device__ uint16_t g_wec[1024*1024];
__device__ uint16_t g_wu1[1024*2048];
__device__ uint16_t g_wu2[1024*1024];
__device__ uint16_t g_wi1[1024*2048];
__device__ float g_c1  [MR*5120];
__device__ float g_cc  [BSZ*DD];
__device__ float g_msg [MR*DD];
__device__ float g_h1  [MR*DD];
__device__ float g_h2  [MR*DD];
__device__ float g_b5  [5120];
__device__ float g_part[BSZ*3];

__constant__ float c_adj[49] = {
    1,1,0,0,1,1,1, 1,1,1,1,1,1,1, 0,1,1,0,1,0,1, 0,1,0,1,1,1,1,
    1,1,1,1,1,1,1, 1,1,0,1,1,1,1, 1,1,1,1,1,1,1};
__constant__ int c_pairs[41] = {
    0,1,4,5,6,
    7,8,9,10,11,12,13,
    15,16,18,20,
    22,24,25,26,27,
    28,29,30,31,32,33,34,
    35,36,38,39,40,41,
    42,43,44,45,46,47,48};

__device__ __forceinline__ float gelu_f(float x) {
    const float x2 = x * x;
    const float u = x * fmaf(0.0356774081f, x2, 0.7978845608f);
    float t;
    asm("tanh.approx.f32 %0, %1;" : "=f"(t) : "f"(u));
    const float hx = 0.5f * x;
    return fmaf(hx, t, hx);
}
__device__ __forceinline__ void mma_f16(float* c, const uint32_t* a, const uint32_t* b) {
    asm volatile(
        "mma.sync.aligned.m16n8k16.row.col.f32.f16.f16.f32 "
        "{%0,%1,%2,%3}, {%4,%5,%6,%7}, {%8,%9}, {%0,%1,%2,%3};"
        : "+f"(c[0]), "+f"(c[1]), "+f"(c[2]), "+f"(c[3])
        : "r"(a[0]), "r"(a[1]), "r"(a[2]), "r"(a[3]), "r"(b[0]), "r"(b[1]));
}
__device__ __forceinline__ void ldsm4(uint32_t* r, uint32_t addr) {
    asm volatile("ldmatrix.sync.aligned.m8n8.x4.shared.b16 {%0,%1,%2,%3}, [%4];"
                 : "=r"(r[0]), "=r"(r[1]), "=r"(r[2]), "=r"(r[3]) : "r"(addr));
}
__device__ __forceinline__ uint32_t smem_u32(const void* p) {
    uint32_t a;
    asm("{ .reg .u64 t; cvta.to.shared.u64 t, %1; cvt.u32.u64 %0, t; }" : "=r"(a) : "l"(p));
    return a;
}

// ---------- fp16 tensor-core GEMM, ldmatrix fragment loads ----------
// C[M,Ncols] = concatA[M,K](fp32->fp16) @ Bt[Ncols,K](fp16)^T
// 128x128 tile, BK=32, 2-stage double buffer, 8 warps (4x2), warp tile 32x64
#define SH   40                   // halves per smem row (80B stride: conflict-free LDSM)
#define MATH (128*SH)
#define STAGEH (2*MATH)

__global__ __launch_bounds__(256, 2)
void gemm_f16(const float* __restrict__ A0, int lda0,
              const float* __restrict__ A1, int lda1, int ksplit, int a1map7,
              const uint16_t* __restrict__ Bt,
              const float* __restrict__ bias, const float* __restrict__ Rres,
              float* __restrict__ C, int ldc, int K, int epi)
{
    extern __shared__ __align__(16) uint16_t sh[];
    const int tid = threadIdx.x, wid = tid >> 5, lane = tid & 31;
    const int m0 = blockIdx.y * 128, n0 = blockIdx.x * 128;
    const int NC = K / 32;
    const int wm = wid & 3, wn = wid >> 2;
    const int gid = lane >> 2, tig = lane & 3;

    const int lrow = tid >> 1;            // 0..127
    const int kb0  = (tid & 1) * 16;      // halves: 0 or 16

    const uint32_t s32 = smem_u32(sh);
    // ldmatrix lane-offsets (bytes within a stage)
    const int ltile = lane >> 3, lr = lane & 7;
    const uint32_t aoff0 = (uint32_t)(((wm * 32 + ((ltile & 1) << 3) + lr) * SH +
                                       ((ltile >> 1) << 3)) * 2);
    const uint32_t aoff1 = aoff0 + 16 * SH * 2;
    uint32_t boff[4];
#pragma unroll
    for (int ntp = 0; ntp < 4; ntp++)
        boff[ntp] = (uint32_t)(MATH * 2 +
            ((wn * 64 + ntp * 16 + ((ltile >> 1) << 3) + lr) * SH + ((ltile & 1) << 3)) * 2);

    float acc[2][8][4];
#pragma unroll
    for (int i = 0; i < 2; i++)
#pragma unroll
        for (int j = 0; j < 8; j++)
#pragma unroll
            for (int q = 0; q < 4; q++) acc[i][j][q] = 0.f;

    float4 ra[4];
    uint4  rb16[2];

#define LOADG(c) do { \
    const int _k0 = (c) * 32; \
    const float* _ap; \
    if (_k0 < ksplit) _ap = A0 + (size_t)(m0 + lrow) * lda0 + _k0; \
    else { \
        int _r = m0 + lrow; \
        if (a1map7) _r = (_r / 7) * 7 + 6; \
        _ap = A1 + (size_t)_r * lda1 + (_k0 - ksplit); \
    } \
    _Pragma("unroll") \
    for (int _j = 0; _j < 4; _j++) ra[_j] = *(const float4*)(_ap + kb0 + 4 * _j); \
    const size_t _bo = (size_t)(n0 + lrow) * K + _k0 + kb0; \
    rb16[0] = *(const uint4*)(Bt + _bo); \
    rb16[1] = *(const uint4*)(Bt + _bo + 8); \
} while (0)

#define STS_STAGE(st) do { \
    uint16_t* _base = sh + (st) * STAGEH; \
    uint16_t _h[16]; \
    _Pragma("unroll") \
    for (int _j = 0; _j < 4; _j++) { \
        _h[4*_j+0] = __half_as_ushort(__float2half_rn(ra[_j].x)); \
        _h[4*_j+1] = __half_as_ushort(__float2half_rn(ra[_j].y)); \
        _h[4*_j+2] = __half_as_ushort(__float2half_rn(ra[_j].z)); \
        _h[4*_j+3] = __half_as_ushort(__float2half_rn(ra[_j].w)); \
    } \
    const int _off = lrow * SH + kb0; \
    *(uint4*)(_base + _off)            = *(uint4*)&_h[0]; \
    *(uint4*)(_base + _off + 8)        = *(uint4*)&_h[8]; \
    *(uint4*)(_base + MATH + _off)     = rb16[0]; \
    *(uint4*)(_base + MATH + _off + 8) = rb16[1]; \
} while (0)

    LOADG(0);
    STS_STAGE(0);
    __syncthreads();

    for (int c = 0; c < NC; c++) {
        if (c + 1 < NC) LOADG(c + 1);

        const uint32_t sb0 = s32 + (uint32_t)((c & 1) * STAGEH * 2);
#pragma unroll
        for (int ks = 0; ks < 2; ks++) {
            const uint32_t koff = (uint32_t)(ks * 32);   // 16 halves
            uint32_t aF0[4], aF1[4];
            ldsm4(aF0, sb0 + aoff0 + koff);
            ldsm4(aF1, sb0 + aoff1 + koff);
#pragma unroll
            for (int ntp = 0; ntp < 4; ntp++) {
                uint32_t bq[4];
                ldsm4(bq, sb0 + boff[ntp] + koff);
                mma_f16(acc[0][2*ntp],     aF0, &bq[0]);
                mma_f16(acc[0][2*ntp + 1], aF0, &bq[2]);
                mma_f16(acc[1][2*ntp],     aF1, &bq[0]);
                mma_f16(acc[1][2*ntp + 1], aF1, &bq[2]);
            }
        }

        if (c + 1 < NC) STS_STAGE((c + 1) & 1);
        __syncthreads();
    }

#pragma unroll
    for (int mt = 0; mt < 2; mt++) {
#pragma unroll
        for (int rr = 0; rr < 2; rr++) {
            const int row = m0 + wm * 32 + mt * 16 + gid + rr * 8;
#pragma unroll
            for (int nt = 0; nt < 8; nt++) {
                const int col = n0 + wn * 64 + nt * 8 + tig * 2;
                float v0 = acc[mt][nt][rr * 2 + 0];
                float v1 = acc[mt][nt][rr * 2 + 1];
                if (bias) { v0 += bias[col]; v1 += bias[col + 1]; }
                if (epi == 1) { v0 = gelu_f(v0); v1 = gelu_f(v1); }
                else if (epi == 2) {
                    const float2 rv = *(const float2*)(Rres + (size_t)row * 1024 + col);
                    v0 += rv.x; v1 += rv.y;
                }
                *(float2*)(C + (size_t)row * ldc + col) = make_float2(v0, v1);
            }
        }
    }
}

// ---------- unified prep ----------
__global__ void prep_all(const float* __restrict__ Wq, const float* __restrict__ Wk,
                         const float* __restrict__ Wv, const float* __restrict__ We1,
                         const float* __restrict__ Wu1, const float* __restrict__ Wu2,
                         const float* __restrict__ Wi1,
                         const float* __restrict__ bq, const float* __restrict__ bk,
                         const float* __restrict__ bv,
                         uint16_t* __restrict__ w5, uint16_t* __restrict__ wec,
                         uint16_t* __restrict__ wu1, uint16_t* __restrict__ wu2,
                         uint16_t* __restrict__ wi1, float* __restrict__ b5)
{
    const int bid = blockIdx.x;
    if (bid >= 11264) {
        const int i = (bid - 11264) * 256 + threadIdx.x;
        if (i < 5120) {
            float v = 0.f;
            if (i < 1024) v = bq[i];
            else if (i < 2048) v = bk[i - 1024];
            else if (i < 3072) v = bv[i - 2048];
            b5[i] = v;
        }
        return;
    }
    const float* src; uint16_t* dst; int K, t;
    if (bid < 5120) {
        const int wsel = bid >> 10; t = bid & 1023;
        src = (wsel == 0) ? Wq : (wsel == 1) ? Wk : (wsel == 2) ? Wv
            : (wsel == 3) ? We1 : (We1 + 1024 * 1024);
        dst = w5 + (size_t)wsel * 1024 * 1024; K = 1024;
    } else if (bid < 6144) { src = We1 + 2 * 1024 * 1024; dst = wec; K = 1024; t = bid - 5120; }
    else if (bid < 8192)  { src = Wu1; dst = wu1; K = 2048; t = bid - 6144; }
    else if (bid < 9216)  { src = Wu2; dst = wu2; K = 1024; t = bid - 8192; }
    else                  { src = Wi1; dst = wi1; K = 2048; t = bid - 9216; }

    const int ktiles = K >> 5;
    const int k0 = (t % ktiles) * 32, n0 = (t / ktiles) * 32;
    __shared__ float tt[32][33];
    const int tx = threadIdx.x & 31, ty = threadIdx.x >> 5;
    for (int i = ty; i < 32; i += 8) tt[i][tx] = src[(size_t)(k0 + i) * 1024 + n0 + tx];
    __syncthreads();
    for (int i = ty; i < 32; i += 8)
        dst[(size_t)(n0 + i) * K + k0 + tx] = __half_as_ushort(__float2half_rn(tt[tx][i]));
}

// ---------- fused attention: float4 fill, active pairs, fast gelu ----------
#define ATT_T 512
__global__ __launch_bounds__(ATT_T, 1)
void attn_kernel(const float* __restrict__ c1, const float* __restrict__ cc,
                 const float* __restrict__ be1, const float* __restrict__ We2,
                 const float* __restrict__ be2,
                 float* __restrict__ attn_out, float* __restrict__ msg)
{
    const int b = blockIdx.x;
    extern __shared__ float sm[];
    float* sq  = sm;
    float* sk  = sq  + NN * DD;
    float* sv  = sk  + NN * DD;
    float* sla = sv  + NN * DD;
    float* srb = sla + NN * DD;
    float* scb = srb + NN * DD;
    float* sw2 = scb + DD;
    __shared__ float s_logits[49];
    __shared__ float s_attn[49];

    const int tid = threadIdx.x;
    const size_t rbase = (size_t)b * NN * 5120;

    for (int i = tid; i < DD / 4; i += ATT_T) {
        const float4 c4 = *(const float4*)(cc + (size_t)b * DD + i * 4);
        const float4 e4 = *(const float4*)(be1 + i * 4);
        ((float4*)scb)[i] = make_float4(c4.x + e4.x, c4.y + e4.y, c4.z + e4.z, c4.w + e4.w);
        ((float4*)sw2)[i] = *(const float4*)(We2 + i * 4);
    }
    __syncthreads();
    for (int i = tid; i < NN * DD / 4; i += ATT_T) {
        const int i4 = i * 4;
        const int n = i4 >> 10, d = i4 & 1023;
        const size_t ro = rbase + (size_t)n * 5120 + d;
        ((float4*)sq)[i] = *(const float4*)(c1 + ro);
        ((float4*)sk)[i] = *(const float4*)(c1 + ro + 1024);
        ((float4*)sv)[i] = *(const float4*)(c1 + ro + 2048);
        const float4 l4 = *(const float4*)(c1 + ro + 3072);
        const float4 b4 = ((const float4*)scb)[d >> 2];
        ((float4*)sla)[i] = make_float4(l4.x + b4.x, l4.y + b4.y, l4.z + b4.z, l4.w + b4.w);
        ((float4*)srb)[i] = *(const float4*)(c1 + ro + 4096);
    }
    if (tid < 49) s_logits[tid] = -1e30f;
    __syncthreads();

    const int warp = tid >> 5, lane = tid & 31;
    const float be2v = be2[0];
    for (int pi = warp; pi < 41; pi += ATT_T / 32) {
        const int p = c_pairs[pi];
        const int n = p / 7, m = p % 7;
        const float* qn = sq  + n * DD;
        const float* km = sk  + m * DD;
        const float* ln = sla + n * DD;
        const float* rm = srb + m * DD;
        float aqk = 0.f, ae = 0.f;
        for (int d = lane; d < DD; d += 32) {
            aqk = fmaf(qn[d], km[d], aqk);
            ae  = fmaf(gelu_f(ln[d] + rm[d]), sw2[d], ae);
        }
#pragma unroll
        for (int o = 16; o; o >>= 1) {
            aqk += __shfl_xor_sync(0xffffffffu, aqk, o);
            ae  += __shfl_xor_sync(0xffffffffu, ae,  o);
        }
        if (lane == 0)
            s_logits[p] = aqk * (1.0f / 32.0f) + ae + be2v;
    }
    __syncthreads();

    if (tid < 7) {
        const int n = tid;
        float mx = -1e30f;
#pragma unroll
        for (int m = 0; m < 7; m++) mx = fmaxf(mx, s_logits[n * 7 + m]);
        float s = 0.f, e[7];
#pragma unroll
        for (int m = 0; m < 7; m++) {
            const float lg = s_logits[n * 7 + m];
            e[m] = (lg > -1e29f) ? expf(lg - mx) : 0.f;
            s += e[m];
        }
        const float inv = 1.0f / s;
#pragma unroll
        for (int m = 0; m < 7; m++) {
            const float a = e[m] * inv;
            s_attn[n * 7 + m] = a;
            attn_out[(size_t)b * 49 + n * 7 + m] = a;
        }
    }
    __syncthreads();

    const size_t obase = (size_t)b * NN * DD;
    for (int i = tid; i < NN * DD / 4; i += ATT_T) {
        const int i4 = i * 4;
        const int n = i4 >> 10, d4 = (i4 & 1023) >> 2;
        float4 s = make_float4(0.f, 0.f, 0.f, 0.f);
#pragma unroll
        for (int m = 0; m < 7; m++) {
            const float a = s_attn[n * 7 + m];
            const float4 v4 = ((const float4*)sv)[m * 256 + d4];
            s.x = fmaf(a, v4.x, s.x); s.y = fmaf(a, v4.y, s.y);
            s.z = fmaf(a, v4.z, s.z); s.w = fmaf(a, v4.w, s.w);
        }
        *(float4*)(msg + obase + i4) = s;
    }
}

// ---------- finalize: 512 threads, float4 fill ----------
#define FIN_T 512
__global__ __launch_bounds__(FIN_T, 1)
void final_kernel(const float* __restrict__ upd, const float* __restrict__ h2,
                  const float* __restrict__ Wi2, const float* __restrict__ bi2,
                  float* __restrict__ out_fused, float* __restrict__ out_imp,
                  float* __restrict__ part)
{
    const int b = blockIdx.x;
    __shared__ float su[NN * DD];
    __shared__ float sf[DD];
    __shared__ float s_dot[49], s_implog[7], s_imp[8], s_dotf[7], s_fn2[1];

    const int tid = threadIdx.x, warp = tid >> 5, lane = tid & 31;
    const size_t base = (size_t)b * NN * DD;
    for (int i = tid; i < NN * DD / 4; i += FIN_T)
        ((float4*)su)[i] = *(const float4*)(upd + base + i * 4);
    __syncthreads();

    for (int p = warp; p < 49; p += FIN_T / 32) {
        const int n = p / 7, m = p % 7;
        float s = 0.f;
        for (int d = lane; d < DD; d += 32) s = fmaf(su[n * DD + d], su[m * DD + d], s);
#pragma unroll
        for (int o = 16; o; o >>= 1) s += __shfl_xor_sync(0xffffffffu, s, o);
        if (lane == 0) s_dot[p] = s;
    }
    if (warp < 7) {
        float s = 0.f;
        for (int d = lane; d < DD; d += 32) s = fmaf(h2[base + warp * DD + d], Wi2[d], s);
#pragma unroll
        for (int o = 16; o; o >>= 1) s += __shfl_xor_sync(0xffffffffu, s, o);
        if (lane == 0) s_implog[warp] = s + bi2[0];
    }
    __syncthreads();

    if (tid == 0) {
        float mx = -1e30f;
#pragma unroll
        for (int n = 0; n < 7; n++) mx = fmaxf(mx, s_implog[n]);
        float e[7], sum = 0.f;
#pragma unroll
        for (int n = 0; n < 7; n++) { e[n] = expf(s_implog[n] - mx); sum += e[n]; }
        float imp[7];
#pragma unroll
        for (int n = 0; n < 7; n++) imp[n] = e[n] / sum;
        const float cap[7] = {1.f,1.f,1.f,0.26f,1.f,1.f,0.24f};
        const float fre[7] = {1.f,1.f,1.f,0.f,1.f,1.f,0.f};
        float capped[7], csum = 0.f, fmass = 0.f;
#pragma unroll
        for (int n = 0; n < 7; n++) {
            capped[n] = fminf(imp[n], cap[n]);
            csum += capped[n]; fmass += imp[n] * fre[n];
        }
        const float residual = fmaxf(1.0f - csum, 0.0f);
        float redis[7], rsum = 0.f;
#pragma unroll
        for (int n = 0; n < 7; n++) {
            const float fs = (fmass > 1e-6f) ? imp[n] * fre[n] / fmaxf(fmass, 1e-6f)
                                             : fre[n] * 0.2f;
            redis[n] = capped[n] + fs * residual;
            rsum += redis[n];
        }
        const float inv = 1.0f / fmaxf(rsum, 1e-6f);
#pragma unroll
        for (int n = 0; n < 7; n++) { s_imp[n] = redis[n] * inv; out_imp[b * 7 + n] = s_imp[n]; }
    }
    __syncthreads();

    for (int d = tid; d < DD; d += FIN_T) {
        float f = 0.f;
#pragma unroll
        for (int n = 0; n < 7; n++) f = fmaf(s_imp[n], su[n * DD + d], f);
        sf[d] = f;
        out_fused[(size_t)b * DD + d] = f;
    }
    __syncthreads();

    if (warp < 7) {
        float s = 0.f;
        for (int d = lane; d < DD; d += 32) s = fmaf(su[warp * DD + d], sf[d], s);
#pragma unroll
        for (int o = 16; o; o >>= 1) s += __shfl_xor_sync(0xffffffffu, s, o);
        if (lane == 0) s_dotf[warp] = s;
    } else if (warp == 7) {
        float s = 0.f;
        for (int d = lane; d < DD; d += 32) s = fmaf(sf[d], sf[d], s);
#pragma unroll
        for (int o = 16; o; o >>= 1) s += __shfl_xor_sync(0xffffffffu, s, o);
        if (lane == 0) s_fn2[0] = s;
    }
    __syncthreads();

    if (tid == 0) {
        float norm[7];
#pragma unroll
        for (int n = 0; n < 7; n++) norm[n] = sqrtf(s_dot[n * 7 + n]);
        const float fnorm = sqrtf(s_fn2[0]);
        float edge = 0.f, non = 0.f, align = 0.f;
#pragma unroll
        for (int n = 0; n < 7; n++) {
#pragma unroll
            for (int m = 0; m < 7; m++) {
                const float cosv = s_dot[n * 7 + m] / fmaxf(norm[n] * norm[m], 1e-8f);
                const float adj = c_adj[n * 7 + m];
                edge += (1.0f - cosv) * adj;
                if (n != m) non += fmaxf(cosv - 0.35f, 0.0f) * (1.0f - adj);
            }
            align += 1.0f - s_dotf[n] / (fmaxf(norm[n], 1e-12f) * fmaxf(fnorm, 1e-12f));
        }
        part[b * 3 + 0] = edge; part[b * 3 + 1] = non; part[b * 3 + 2] = align;
    }
}

__global__ void loss_reduce_kernel(const float* __restrict__ part, float* __restrict__ out)
{
    __shared__ float se[256], sn[256], sa[256];
    const int t = threadIdx.x;
    float e = 0.f, n = 0.f, a = 0.f;
    for (int i = t; i < BSZ; i += 256) {
        e += part[i * 3 + 0]; n += part[i * 3 + 1]; a += part[i * 3 + 2];
    }
    se[t] = e; sn[t] = n; sa[t] = a;
    __syncthreads();
    for (int s = 128; s; s >>= 1) {
        if (t < s) { se[t] += se[t+s]; sn[t] += sn[t+s]; sa[t] += sa[t+s]; }
        __syncthreads();
    }
    if (t == 0) {
        out[OFF_PHYS]  = se[0] / 41.0f + 0.5f * (sn[0] / 8.0f);
        out[OFF_ALIGN] = sa[0] / 7168.0f;
    }
}

// ---------- host ----------
extern "C" void kernel_launch(void* const* d_in, const int* in_sizes, int n_in,
                              void* d_out, int out_size)
{
    (void)in_sizes; (void)n_in; (void)out_size;
    const float* nodes = (const float*)d_in[0];
    const float* Wq  = (const float*)d_in[1];  const float* bq  = (const float*)d_in[2];
    const float* Wk  = (const float*)d_in[3];  const float* bk  = (const float*)d_in[4];
    const float* Wv  = (const float*)d_in[5];  const float* bv  = (const float*)d_in[6];
    const float* We1 = (const float*)d_in[7];  const float* be1 = (const float*)d_in[8];
    const float* We2 = (const float*)d_in[9];  const float* be2 = (const float*)d_in[10];
    const float* Wu1 = (const float*)d_in[11]; const float* bu1 = (const float*)d_in[12];
    const float* Wu2 = (const float*)d_in[13]; const float* bu2 = (const float*)d_in[14];
    const float* Wi1 = (const float*)d_in[15]; const float* bi1 = (const float*)d_in[16];
    const float* Wi2 = (const float*)d_in[17]; const float* bi2 = (const float*)d_in[18];
    float* out = (float*)d_out;

    uint16_t *w5, *wec, *wu1, *wu2, *wi1;
    float *c1, *cc, *msg, *h1, *h2, *b5, *part;
    cudaGetSymbolAddress((void**)&w5,  g_w5);
    cudaGetSymbolAddress((void**)&wec, g_wec);
    cudaGetSymbolAddress((void**)&wu1, g_wu1);
    cudaGetSymbolAddress((void**)&wu2, g_wu2);
    cudaGetSymbolAddress((void**)&wi1, g_wi1);
    cudaGetSymbolAddress((void**)&c1,  g_c1);
    cudaGetSymbolAddress((void**)&cc,  g_cc);
    cudaGetSymbolAddress((void**)&msg, g_msg);
    cudaGetSymbolAddress((void**)&h1,  g_h1);
    cudaGetSymbolAddress((void**)&h2,  g_h2);
    cudaGetSymbolAddress((void**)&b5,  g_b5);
    cudaGetSymbolAddress((void**)&part, g_part);

    const int SMEMG = 2 * STAGEH * (int)sizeof(uint16_t);   // 40960
    cudaFuncSetAttribute(gemm_f16, cudaFuncAttributeMaxDynamicSharedMemorySize, SMEMG);
    const int attn_smem = (5 * NN * DD + 2 * DD) * (int)sizeof(float);
    cudaFuncSetAttribute(attn_kernel, cudaFuncAttributeMaxDynamicSharedMemorySize, attn_smem);

    const dim3 blk(256);
    // 1: weight prep
    prep_all<<<11284, blk>>>(Wq, Wk, Wv, We1, Wu1, Wu2, Wi1, bq, bk, bv,
                             w5, wec, wu1, wu2, wi1, b5);

    const int BIGK = 1 << 30;
    // 2: C1[7168,5120] = nodes @ [Wq|Wk|Wv|Wea|Web]
    gemm_f16<<<dim3(40, 56), blk, SMEMG>>>(nodes, 1024, nullptr, 0, BIGK, 0,
                                           w5, b5, nullptr, c1, 5120, 1024, 0);
    // 3: cc = nodes[:,-1] @ Wec
    gemm_f16<<<dim3(8, 8), blk, SMEMG>>>(nodes + 6 * 1024, 7168, nullptr, 0, BIGK, 0,
                                         wec, nullptr, nullptr, cc, 1024, 1024, 0);
    // 4: attention
    attn_kernel<<<BSZ, dim3(ATT_T), attn_smem>>>(c1, cc, be1, We2, be2, out + OFF_ATTN, msg);
    // 5: h1 = gelu(cat(nodes,msg) @ Wu1 + bu1)
    gemm_f16<<<dim3(8, 56), blk, SMEMG>>>(nodes, 1024, msg, 1024, 1024, 0,
                                          wu1, bu1, nullptr, h1, 1024, 2048, 1);
    // 6 (ncu target): updated = h1 @ Wu2 + bu2 + nodes
    gemm_f16<<<dim3(8, 56), blk, SMEMG>>>(h1, 1024, nullptr, 0, BIGK, 0,
                                          wu2, bu2, nodes, out + OFF_UPD, 1024, 1024, 2);
    // 7: h2 = gelu(cat(updated, gq) @ Wi1 + bi1), gq fused via row remap r->(r/7)*7+6
    gemm_f16<<<dim3(8, 56), blk, SMEMG>>>(out + OFF_UPD, 1024, out + OFF_UPD, 1024, 1024, 1,
                                          wi1, bi1, nullptr, h2, 1024, 2048, 1);
    // 8, 9
    final_kernel<<<BSZ, dim3(FIN_T)>>>(out + OFF_UPD, h2, Wi2, bi2, out, out + OFF_IMP, part);
    loss_reduce_kernel<<<1, blk>>>(part, out);
}